// round 5
// baseline (speedup 1.0000x reference)
#include <cuda_runtime.h>

// ---------------- problem constants ----------------
#define Bc    32
#define Nc    1024
#define Ac    16
#define Ec    4096
#define FINc  16
#define Hc    64
#define MIDc  208          // F_IN + 3*H
#define NODES 32768        // B*N
#define ROWSc 524288       // B*A*N
#define NEDGE 131072       // B*E
#define NCHUNK 2048        // NODES/16

// ---------------- scratch (device globals; no allocation) ----------------
__device__ float g_xc[NODES * MIDc];       // concatenated conv features
__device__ float g_agg[NODES * Hc];        // scatter-add buffer
__device__ float g_np[NODES * MIDc];       // node_proj = xc @ W1[208:416]
__device__ float g_ag[Bc * Ac * MIDc];     // gathered agent rows
__device__ float g_pre1[Bc * Ac * MIDc];   // agent rows @ W1[0:208]
__device__ float g_ewp[MIDc];
__device__ float g_cb[MIDc];
__device__ float g_alpha[MIDc];
__device__ float g_beta[MIDc];
__device__ float g_part[NCHUNK * 2 * MIDc];
__device__ float g_logits[ROWSc];

// ---------------- kernels ----------------
__global__ void k_zero_agg(int n) {
    int i = blockIdx.x * blockDim.x + threadIdx.x;
    if (i < n) g_agg[i] = 0.f;
}

__global__ void k_copy_x0(const float* __restrict__ xin) {
    int i = blockIdx.x * blockDim.x + threadIdx.x;
    if (i >= NODES * FINc) return;
    int node = i / FINc, f = i - node * FINc;
    g_xc[node * MIDc + f] = xin[i];
}

// scatter-add x[src] into g_agg[dst]; one thread per (edge, 4 features)
__global__ void k_scatter(const float* __restrict__ xin, int useXc, int colOff,
                          int xs, const int* __restrict__ links, int F) {
    int i = blockIdx.x * blockDim.x + threadIdx.x;
    int nf4 = F >> 2;
    if (i >= NEDGE * nf4) return;
    int e  = i / nf4, f4 = i - e * nf4;
    int b  = e >> 12;          // /4096
    int el = e & 4095;
    const int* lb = links + b * 2 * Ec;
    int srcl = lb[el];
    int dstl = lb[Ec + el];
    const float* xp = useXc ? (g_xc + colOff) : xin;
    const float4 v = *reinterpret_cast<const float4*>(xp + (size_t)(b * Nc + srcl) * xs + f4 * 4);
    float* d = g_agg + (size_t)(b * Nc + dstl) * F + f4 * 4;
    atomicAdd(d + 0, v.x); atomicAdd(d + 1, v.y);
    atomicAdd(d + 2, v.z); atomicAdd(d + 3, v.w);
}

// per-node: agg @ W + b, LayerNorm(64), ReLU -> g_xc column slice
__global__ void k_gin_mlp(int F, const float* __restrict__ W,
                          const float* __restrict__ bias,
                          const float* __restrict__ g,
                          const float* __restrict__ beta, int colOff) {
    int node = blockIdx.x;
    int h = threadIdx.x;   // 64 threads
    __shared__ float sa[Hc];
    if (h < F) sa[h] = g_agg[(size_t)node * F + h];
    __syncthreads();
    float s = bias[h];
    #pragma unroll 16
    for (int f = 0; f < F; f++) s = fmaf(sa[f], W[f * Hc + h], s);
    float v1 = s, v2 = s * s;
    #pragma unroll
    for (int o = 16; o; o >>= 1) {
        v1 += __shfl_xor_sync(0xffffffffu, v1, o);
        v2 += __shfl_xor_sync(0xffffffffu, v2, o);
    }
    __shared__ float r1[2], r2[2];
    int wid = h >> 5;
    if ((h & 31) == 0) { r1[wid] = v1; r2[wid] = v2; }
    __syncthreads();
    float sum = r1[0] + r1[1], sq = r2[0] + r2[1];
    float mean = sum * (1.f / Hc);
    float var = sq * (1.f / Hc) - mean * mean;
    float y = (s - mean) * rsqrtf(var + 1e-5f) * g[h] + beta[h];
    g_xc[(size_t)node * MIDc + colOff + h] = fmaxf(y, 0.f);
}

__global__ void k_gather(const int* __restrict__ loc) {
    int i = blockIdx.x * blockDim.x + threadIdx.x;
    if (i >= Bc * Ac * MIDc) return;
    int r = i / MIDc, k = i - r * MIDc;
    int b = r / Ac;
    int node = b * Nc + loc[r];
    g_ag[i] = g_xc[(size_t)node * MIDc + k];
}

// C[M,208] = A[M,208] @ W[208,208]; mode 0: xc->np, mode 1: ag->pre1
#define BMt 64
#define BNt 64
#define BKt 16
__global__ void __launch_bounds__(256) k_sgemm(const float* __restrict__ W, int M, int mode) {
    const float* A = mode ? g_ag : g_xc;
    float* C       = mode ? g_pre1 : g_np;
    const int K = MIDc, NN = MIDc;
    __shared__ float As[BKt][BMt + 1];
    __shared__ float Ws[BKt][BNt];
    int bn = blockIdx.x * BNt, bm = blockIdx.y * BMt;
    int tid = threadIdx.x;
    int tx = tid & 15, ty = tid >> 4;
    float acc[4][4] = {};
    for (int k0 = 0; k0 < K; k0 += BKt) {
        #pragma unroll
        for (int i = tid; i < BMt * BKt; i += 256) {
            int r = i >> 4, c = i & 15;
            As[c][r] = A[(size_t)(bm + r) * K + k0 + c];
        }
        #pragma unroll
        for (int i = tid; i < BKt * BNt; i += 256) {
            int r = i >> 6, c = i & 63;
            int col = bn + c;
            Ws[r][c] = (col < NN) ? W[(size_t)(k0 + r) * NN + col] : 0.f;
        }
        __syncthreads();
        #pragma unroll
        for (int kk = 0; kk < BKt; kk++) {
            float av[4], wv[4];
            #pragma unroll
            for (int i = 0; i < 4; i++) av[i] = As[kk][ty * 4 + i];
            #pragma unroll
            for (int j = 0; j < 4; j++) wv[j] = Ws[kk][tx * 4 + j];
            #pragma unroll
            for (int i = 0; i < 4; i++)
                #pragma unroll
                for (int j = 0; j < 4; j++)
                    acc[i][j] = fmaf(av[i], wv[j], acc[i][j]);
        }
        __syncthreads();
    }
    #pragma unroll
    for (int i = 0; i < 4; i++) {
        int row = bm + ty * 4 + i;
        #pragma unroll
        for (int j = 0; j < 4; j++) {
            int col = bn + tx * 4 + j;
            if (col < NN) C[(size_t)row * NN + col] = acc[i][j];
        }
    }
}

// ew_proj[m] = edges_W . W1[416+h,m]; cb[m] = actor1_b[m] + edges_b . W1[416+h,m]
__global__ void k_ewp(const float* __restrict__ eW, const float* __restrict__ eb,
                      const float* __restrict__ W1, const float* __restrict__ b1) {
    int m = threadIdx.x;
    if (m >= MIDc) return;
    float s = 0.f, t = 0.f;
    #pragma unroll 8
    for (int h2 = 0; h2 < Hc; h2++) {
        float w = W1[(size_t)(2 * MIDc + h2) * MIDc + m];
        s = fmaf(eW[h2], w, s);
        t = fmaf(eb[h2], w, t);
    }
    g_ewp[m] = s;
    g_cb[m]  = t + b1[m];
}

// stats pass: block handles 16 consecutive (b,n); per-feature s1,s2 partials
__global__ void __launch_bounds__(256) k_stats(const int* __restrict__ loc,
                                               const float* __restrict__ dist) {
    int chunk = blockIdx.x;
    int p0 = chunk * 16;
    int b = p0 >> 10;
    int m = threadIdx.x;   // 256
    __shared__ float sp[Ac * MIDc];
    __shared__ float sd[16 * Ac];
    __shared__ int sloc[Ac];
    if (m < Ac) sloc[m] = loc[b * Ac + m];
    for (int i = m; i < Ac * MIDc; i += 256) sp[i] = g_pre1[(size_t)b * Ac * MIDc + i];
    __syncthreads();
    for (int i = m; i < 16 * Ac; i += 256) {
        int ii = i >> 4, a = i & 15;
        int n = (p0 + ii) & 1023;
        sd[i] = dist[(size_t)sloc[a] * Nc + n];
    }
    __syncthreads();
    if (m < MIDc) {
        float e = g_ewp[m], c = g_cb[m];
        float s1 = 0.f, s2 = 0.f;
        for (int ii = 0; ii < 16; ii++) {
            int n = (p0 + ii) & 1023;
            float base = g_np[(size_t)(b * Nc + n) * MIDc + m] + c;
            #pragma unroll
            for (int a = 0; a < Ac; a++) {
                float h = base + sp[a * MIDc + m] + sd[ii * Ac + a] * e;
                s1 += h;
                s2 = fmaf(h, h, s2);
            }
        }
        g_part[(size_t)chunk * (2 * MIDc) + m]        = s1;
        g_part[(size_t)chunk * (2 * MIDc) + MIDc + m] = s2;
    }
}

__global__ void k_reduce(const float* __restrict__ bn_g, const float* __restrict__ bn_b) {
    int m = threadIdx.x;
    if (m >= MIDc) return;
    double s1 = 0.0, s2 = 0.0;
    for (int c = 0; c < NCHUNK; c++) {
        s1 += (double)g_part[(size_t)c * (2 * MIDc) + m];
        s2 += (double)g_part[(size_t)c * (2 * MIDc) + MIDc + m];
    }
    double inv = 1.0 / (double)ROWSc;
    double mu = s1 * inv;
    double var = s2 * inv - mu * mu;
    float al = bn_g[m] * (float)rsqrt(var + 1e-5);
    g_alpha[m] = al;
    g_beta[m]  = bn_b[m] - (float)mu * al;
}

// final: BN+ReLU+actor2 dot + mask, block = 16 warps (warp=agent) x 16 node rows
// mask read as 32-bit words: handles both int32{0,1} and float32{0.0,1.0}
// encodings of the original bool array (nonzero bits <=> true).
__global__ void __launch_bounds__(512) k_final(const int* __restrict__ loc,
                                               const float* __restrict__ dist,
                                               const float* __restrict__ W2,
                                               const float* __restrict__ b2,
                                               const int* __restrict__ mask) {
    int chunk = blockIdx.x;
    int p0 = chunk * 16;
    int b = p0 >> 10;
    int tid = threadIdx.x;         // 512
    int a = tid >> 5, lane = tid & 31;
    __shared__ float sp[Ac * MIDc];
    __shared__ float sal[MIDc], sbe[MIDc], sw2[MIDc], sewp[MIDc], scb[MIDc];
    __shared__ int sloc[Ac];
    for (int i = tid; i < Ac * MIDc; i += 512) sp[i] = g_pre1[(size_t)b * Ac * MIDc + i];
    if (tid < MIDc) {
        sal[tid] = g_alpha[tid]; sbe[tid] = g_beta[tid];
        sw2[tid] = W2[tid]; sewp[tid] = g_ewp[tid]; scb[tid] = g_cb[tid];
    }
    if (tid < Ac) sloc[tid] = loc[b * Ac + tid];
    __syncthreads();
    float bb2 = b2[0];
    for (int ii = 0; ii < 16; ii++) {
        int n = (p0 + ii) & 1023;
        float d = dist[(size_t)sloc[a] * Nc + n];
        float part = 0.f;
        for (int m = lane; m < MIDc; m += 32) {
            float h = g_np[(size_t)(b * Nc + n) * MIDc + m] + sp[a * MIDc + m]
                      + d * sewp[m] + scb[m];
            float y = fmaxf(fmaf(sal[m], h, sbe[m]), 0.f);
            part = fmaf(y, sw2[m], part);
        }
        #pragma unroll
        for (int o = 16; o; o >>= 1) part += __shfl_xor_sync(0xffffffffu, part, o);
        if (lane == 0) {
            int ridx = b * (Ac * Nc) + a * Nc + n;
            float lg = part + bb2;
            g_logits[ridx] = (mask[ridx] != 0) ? lg : -1e8f;
        }
    }
}

__global__ void __launch_bounds__(1024) k_softmax(float* __restrict__ out) {
    int b = blockIdx.x, tid = threadIdx.x;
    const float* L = g_logits + (size_t)b * Ac * Nc;
    __shared__ float red[32];
    __shared__ float sval;
    float mx = -3.4028235e38f;
    for (int i = tid; i < Ac * Nc; i += 1024) mx = fmaxf(mx, L[i]);
    #pragma unroll
    for (int o = 16; o; o >>= 1) mx = fmaxf(mx, __shfl_xor_sync(0xffffffffu, mx, o));
    if ((tid & 31) == 0) red[tid >> 5] = mx;
    __syncthreads();
    if (tid < 32) {
        float v = red[tid];
        #pragma unroll
        for (int o = 16; o; o >>= 1) v = fmaxf(v, __shfl_xor_sync(0xffffffffu, v, o));
        if (tid == 0) sval = v;
    }
    __syncthreads();
    mx = sval;
    float s = 0.f;
    for (int i = tid; i < Ac * Nc; i += 1024) s += expf(L[i] - mx);
    #pragma unroll
    for (int o = 16; o; o >>= 1) s += __shfl_xor_sync(0xffffffffu, s, o);
    __syncthreads();
    if ((tid & 31) == 0) red[tid >> 5] = s;
    __syncthreads();
    if (tid < 32) {
        float v = red[tid];
        #pragma unroll
        for (int o = 16; o; o >>= 1) v += __shfl_xor_sync(0xffffffffu, v, o);
        if (tid == 0) sval = v;
    }
    __syncthreads();
    float inv = 1.f / sval;
    for (int i = tid; i < Ac * Nc; i += 1024)
        out[(size_t)b * Ac * Nc + i] = expf(L[i] - mx) * inv;
}

// ---------------- launch ----------------
extern "C" void kernel_launch(void* const* d_in, const int* in_sizes, int n_in,
                              void* d_out, int out_size) {
    const float* gnodes = (const float*)d_in[0];
    const int*   links  = (const int*)d_in[1];
    const int*   loc    = (const int*)d_in[2];
    const int*   mask   = (const int*)d_in[3];   // bool marshalled as 32-bit (int32 or f32)
    const float* dist   = (const float*)d_in[4];
    const float* cW[3]  = {(const float*)d_in[5],  (const float*)d_in[9],  (const float*)d_in[13]};
    const float* cb_[3] = {(const float*)d_in[6],  (const float*)d_in[10], (const float*)d_in[14]};
    const float* cg[3]  = {(const float*)d_in[7],  (const float*)d_in[11], (const float*)d_in[15]};
    const float* cbe[3] = {(const float*)d_in[8],  (const float*)d_in[12], (const float*)d_in[16]};
    const float* eW  = (const float*)d_in[17];
    const float* eb  = (const float*)d_in[18];
    const float* W1  = (const float*)d_in[19];
    const float* b1  = (const float*)d_in[20];
    const float* bng = (const float*)d_in[21];
    const float* bnb = (const float*)d_in[22];
    const float* W2  = (const float*)d_in[23];
    const float* b2  = (const float*)d_in[24];
    float* out = (float*)d_out;

    // 1. x0 -> xc[:,0:16]
    k_copy_x0<<<(NODES * FINc + 255) / 256, 256>>>(gnodes);

    // 2. three GIN conv layers
    const int inF[3]    = {FINc, Hc, Hc};
    const int inOff[3]  = {0, 16, 80};
    const int outOff[3] = {16, 80, 144};
    for (int l = 0; l < 3; l++) {
        int F = inF[l];
        int nAgg = NODES * F;
        k_zero_agg<<<(nAgg + 255) / 256, 256>>>(nAgg);
        int nSc = NEDGE * (F / 4);
        k_scatter<<<(nSc + 255) / 256, 256>>>(gnodes, l > 0 ? 1 : 0, inOff[l],
                                              l > 0 ? MIDc : FINc, links, F);
        k_gin_mlp<<<NODES, 64>>>(F, cW[l], cb_[l], cg[l], cbe[l], outOff[l]);
    }

    // 3. gather agent rows
    k_gather<<<(Bc * Ac * MIDc + 255) / 256, 256>>>(loc);

    // 4. pre1 = ag @ W1[0:208] ; node_proj = xc @ W1[208:416]
    {
        dim3 gp((MIDc + BNt - 1) / BNt, (Bc * Ac) / BMt);      // 4 x 8
        k_sgemm<<<gp, 256>>>(W1, Bc * Ac, 1);
        dim3 gn((MIDc + BNt - 1) / BNt, NODES / BMt);          // 4 x 512
        k_sgemm<<<gn, 256>>>(W1 + (size_t)MIDc * MIDc, NODES, 0);
    }

    // 5. edge projection
    k_ewp<<<1, 256>>>(eW, eb, W1, b1);

    // 6. BatchNorm stats
    k_stats<<<NCHUNK, 256>>>(loc, dist);
    k_reduce<<<1, 256>>>(bng, bnb);

    // 7. final logits (BN + ReLU + actor2 + mask)
    k_final<<<NCHUNK, 512>>>(loc, dist, W2, b2, mask);

    // 8. per-batch softmax
    k_softmax<<<Bc, 1024>>>(out);
}

// round 7
// speedup vs baseline: 1.3617x; 1.3617x over previous
#include <cuda_runtime.h>

// ---------------- problem constants ----------------
#define Bc    32
#define Nc    1024
#define Ac    16
#define Ec    4096
#define FINc  16
#define Hc    64
#define MIDc  208          // F_IN + 3*H
#define NODES 32768        // B*N
#define ROWSc 524288       // B*A*N
#define NEDGE 131072       // B*E
#define NFCHUNK 2048       // final chunks (16 nodes each)
#define NSCHUNK 256        // stats chunks (128 nodes each)

// ---------------- scratch (device globals; referenced ONLY from device code) --
__device__ float g_xc[NODES * MIDc];       // concatenated conv features
__device__ float g_np[NODES * MIDc];       // node_proj = xc @ W1[208:416]
__device__ float g_ag[Bc * Ac * MIDc];     // gathered agent rows
__device__ float g_pre1[Bc * Ac * MIDc];   // agent rows @ W1[0:208]
__device__ float g_ewp[MIDc];
__device__ float g_cb[MIDc];
__device__ float g_alpha[MIDc];
__device__ float g_beta[MIDc];
__device__ float g_logits[ROWSc];
// CSR
__device__ int   g_cnt[NODES];
__device__ int   g_fill[NODES];
__device__ int   g_rowptr[NODES + 1];
__device__ int   g_col[NEDGE];
// closed-form BN stats
__device__ float g_D[NODES];               // D[b,n] = sum_a dist[loc,n]
__device__ float g_Da[Bc * Ac];            // Da[b,a] = sum_n dist[loc,n]
__device__ float g_sd2p[Bc];               // per-b sum of d^2
__device__ float g_p2[NSCHUNK * 3 * MIDc]; // per-chunk {S1np, S2np, SnpD}

// ================= CSR build =================
__global__ void k_zero2() {
    int i = blockIdx.x * blockDim.x + threadIdx.x;
    if (i < NODES) { g_cnt[i] = 0; g_fill[i] = 0; }
}

__global__ void k_count(const int* __restrict__ links) {
    int i = blockIdx.x * blockDim.x + threadIdx.x;
    if (i >= NEDGE) return;
    int b = i >> 12, e = i & 4095;
    int dst = links[b * 2 * Ec + Ec + e];
    atomicAdd(&g_cnt[b * Nc + dst], 1);
}

__global__ void __launch_bounds__(1024) k_scan() {
    int b = blockIdx.x, t = threadIdx.x;
    __shared__ int s[1024];
    int v = g_cnt[b * Nc + t];
    s[t] = v;
    __syncthreads();
    for (int off = 1; off < 1024; off <<= 1) {
        int x = (t >= off) ? s[t - off] : 0;
        __syncthreads();
        s[t] += x;
        __syncthreads();
    }
    g_rowptr[b * Nc + t] = b * Ec + s[t] - v;   // exclusive prefix
    if (b == Bc - 1 && t == 1023) g_rowptr[NODES] = NEDGE;
}

__global__ void k_fill(const int* __restrict__ links) {
    int i = blockIdx.x * blockDim.x + threadIdx.x;
    if (i >= NEDGE) return;
    int b = i >> 12, e = i & 4095;
    int src = links[b * 2 * Ec + e];
    int dst = links[b * 2 * Ec + Ec + e];
    int node = b * Nc + dst;
    int pos = g_rowptr[node] + atomicAdd(&g_fill[node], 1);
    g_col[pos] = b * Nc + src;
}

// ================= input copy =================
__global__ void k_copy_x0(const float* __restrict__ xin) {
    int i = blockIdx.x * blockDim.x + threadIdx.x;
    if (i >= NODES * FINc) return;
    int node = i >> 4, f = i & 15;
    g_xc[node * MIDc + f] = xin[i];
}

// ================= fused conv layer: gather-agg + MLP + LN + ReLU =========
// block = 512 threads handles 32 nodes. thread: h = tid&63, tg = tid>>6,
// nodes = base + tg*4 + {0..3}.  Input pointer resolved in DEVICE code.
template <int F>
__global__ void __launch_bounds__(512) k_conv(const float* __restrict__ gnodes,
                                              const float* __restrict__ W,
                                              const float* __restrict__ bias,
                                              const float* __restrict__ gg,
                                              const float* __restrict__ beta,
                                              int layer) {
    const float* X;
    int xs, outOff;
    if (layer == 0)      { X = gnodes;    xs = FINc; outOff = 16; }
    else if (layer == 1) { X = g_xc + 16; xs = MIDc; outOff = 80; }
    else                 { X = g_xc + 80; xs = MIDc; outOff = 144; }

    int tid = threadIdx.x;
    int h = tid & 63, tg = tid >> 6;
    int base = blockIdx.x * 32;
    __shared__ float sW[F * 64];
    __shared__ float sagg[32][64];
    __shared__ float sbias[64], sg[64], sb[64];
    __shared__ float red1[8][2][4], red2[8][2][4];
    for (int i = tid; i < F * 64; i += 512) sW[i] = W[i];
    if (tid < 64) { sbias[tid] = bias[tid]; sg[tid] = gg[tid]; sb[tid] = beta[tid]; }
    // phase A: aggregate
    if (h < F) {
        #pragma unroll
        for (int j = 0; j < 4; j++) {
            int node = base + tg * 4 + j;
            int p0 = g_rowptr[node], p1 = g_rowptr[node + 1];
            float s = 0.f;
            for (int p = p0; p < p1; p++) s += X[(size_t)g_col[p] * xs + h];
            sagg[tg * 4 + j][h] = s;
        }
    }
    __syncthreads();
    // phase B: MLP (4 nodes per thread, f unrolled x4 for vec4 agg loads)
    float acc[4];
    #pragma unroll
    for (int j = 0; j < 4; j++) acc[j] = sbias[h];
    #pragma unroll
    for (int f = 0; f < F; f += 4) {
        float w0 = sW[(f + 0) * 64 + h];
        float w1 = sW[(f + 1) * 64 + h];
        float w2 = sW[(f + 2) * 64 + h];
        float w3 = sW[(f + 3) * 64 + h];
        #pragma unroll
        for (int j = 0; j < 4; j++) {
            float4 a = *reinterpret_cast<const float4*>(&sagg[tg * 4 + j][f]);
            acc[j] = fmaf(a.x, w0, acc[j]);
            acc[j] = fmaf(a.y, w1, acc[j]);
            acc[j] = fmaf(a.z, w2, acc[j]);
            acc[j] = fmaf(a.w, w3, acc[j]);
        }
    }
    // LN over the 64 h-values per node
    float v1[4], v2[4];
    #pragma unroll
    for (int j = 0; j < 4; j++) { v1[j] = acc[j]; v2[j] = acc[j] * acc[j]; }
    #pragma unroll
    for (int o = 16; o; o >>= 1) {
        #pragma unroll
        for (int j = 0; j < 4; j++) {
            v1[j] += __shfl_xor_sync(0xffffffffu, v1[j], o);
            v2[j] += __shfl_xor_sync(0xffffffffu, v2[j], o);
        }
    }
    int wh = h >> 5;
    if ((h & 31) == 0) {
        #pragma unroll
        for (int j = 0; j < 4; j++) { red1[tg][wh][j] = v1[j]; red2[tg][wh][j] = v2[j]; }
    }
    __syncthreads();
    #pragma unroll
    for (int j = 0; j < 4; j++) {
        float sum = red1[tg][0][j] + red1[tg][1][j];
        float sq  = red2[tg][0][j] + red2[tg][1][j];
        float mean = sum * (1.f / 64.f);
        float var  = sq * (1.f / 64.f) - mean * mean;
        float y = (acc[j] - mean) * rsqrtf(var + 1e-5f) * sg[h] + sb[h];
        int node = base + tg * 4 + j;
        g_xc[(size_t)node * MIDc + outOff + h] = fmaxf(y, 0.f);
    }
}

// ================= gather agent rows =================
__global__ void k_gather(const int* __restrict__ loc) {
    int i = blockIdx.x * blockDim.x + threadIdx.x;
    if (i >= Bc * Ac * MIDc) return;
    int r = i / MIDc, k = i - r * MIDc;
    int b = r >> 4;
    int node = b * Nc + loc[r];
    g_ag[i] = g_xc[(size_t)node * MIDc + k];
}

// ================= tiled SGEMM: C[M,208] = A[M,208] @ W[208,208] ==========
// mode 0: A = g_xc, C = g_np ; mode 1: A = g_ag, C = g_pre1 (device-resolved)
#define GM 128
#define GN 112
#define GK 8
__global__ void __launch_bounds__(256) k_gemm208(const float* __restrict__ W, int mode) {
    const float* A = mode ? g_ag : g_xc;
    float* C       = mode ? g_pre1 : g_np;
    __shared__ float As[2][GK][GM];
    __shared__ float Ws[2][GK][GN];
    int bm = blockIdx.y * GM;
    int bn = blockIdx.x * GN;         // 0 or 112
    int tid = threadIdx.x;
    int tx = tid & 15;                // rows tx*8 .. +7
    int ty = tid >> 4;                // cols ty*7 .. +6
    int am = tid >> 1, ah = (tid & 1) * 4;
    float acc[8][7];
    #pragma unroll
    for (int i = 0; i < 8; i++)
        #pragma unroll
        for (int j = 0; j < 7; j++) acc[i][j] = 0.f;

    // prologue: chunk 0
    {
        float4 v = *reinterpret_cast<const float4*>(&A[(size_t)(bm + am) * MIDc + ah]);
        As[0][ah + 0][am] = v.x; As[0][ah + 1][am] = v.y;
        As[0][ah + 2][am] = v.z; As[0][ah + 3][am] = v.w;
        for (int i = tid; i < GK * GN; i += 256) {
            int r = i / GN, c = i - r * GN;
            int col = bn + c;
            Ws[0][r][c] = (col < MIDc) ? W[(size_t)r * MIDc + col] : 0.f;
        }
    }
    __syncthreads();
    const int nk = MIDc / GK;  // 26
    float4 pa;
    float pw[4];
    for (int kc = 0; kc < nk; kc++) {
        int cur = kc & 1;
        if (kc + 1 < nk) {
            int k0 = (kc + 1) * GK;
            pa = *reinterpret_cast<const float4*>(&A[(size_t)(bm + am) * MIDc + k0 + ah]);
            int t = 0;
            for (int i = tid; i < GK * GN; i += 256, t++) {
                int r = i / GN, c = i - r * GN;
                int col = bn + c;
                pw[t] = (col < MIDc) ? W[(size_t)(k0 + r) * MIDc + col] : 0.f;
            }
        }
        #pragma unroll
        for (int kk = 0; kk < GK; kk++) {
            float a[8], bv[7];
            *reinterpret_cast<float4*>(&a[0]) = *reinterpret_cast<float4*>(&As[cur][kk][tx * 8]);
            *reinterpret_cast<float4*>(&a[4]) = *reinterpret_cast<float4*>(&As[cur][kk][tx * 8 + 4]);
            #pragma unroll
            for (int j = 0; j < 7; j++) bv[j] = Ws[cur][kk][ty * 7 + j];
            #pragma unroll
            for (int i = 0; i < 8; i++)
                #pragma unroll
                for (int j = 0; j < 7; j++)
                    acc[i][j] = fmaf(a[i], bv[j], acc[i][j]);
        }
        if (kc + 1 < nk) {
            int nxt = cur ^ 1;
            As[nxt][ah + 0][am] = pa.x; As[nxt][ah + 1][am] = pa.y;
            As[nxt][ah + 2][am] = pa.z; As[nxt][ah + 3][am] = pa.w;
            int t = 0;
            for (int i = tid; i < GK * GN; i += 256, t++) {
                int r = i / GN, c = i - r * GN;
                Ws[nxt][r][c] = pw[t];
            }
        }
        __syncthreads();
    }
    #pragma unroll
    for (int i = 0; i < 8; i++) {
        int row = bm + tx * 8 + i;
        #pragma unroll
        for (int j = 0; j < 7; j++) {
            int col = bn + ty * 7 + j;
            if (col < MIDc) C[(size_t)row * MIDc + col] = acc[i][j];
        }
    }
}

// ================= edge projection =================
__global__ void k_ewp(const float* __restrict__ eW, const float* __restrict__ eb,
                      const float* __restrict__ W1, const float* __restrict__ b1) {
    int m = threadIdx.x;
    if (m >= MIDc) return;
    float s = 0.f, t = 0.f;
    #pragma unroll 8
    for (int h2 = 0; h2 < Hc; h2++) {
        float w = W1[(size_t)(2 * MIDc + h2) * MIDc + m];
        s = fmaf(eW[h2], w, s);
        t = fmaf(eb[h2], w, t);
    }
    g_ewp[m] = s;
    g_cb[m]  = t + b1[m];
}

// ================= dist row/col sums =================
__global__ void __launch_bounds__(512) k_dsums(const int* __restrict__ loc,
                                               const float* __restrict__ dist) {
    int b = blockIdx.x, tid = threadIdx.x;
    __shared__ int sloc[Ac];
    __shared__ float rsd[16];
    if (tid < Ac) sloc[tid] = loc[b * Ac + tid];
    __syncthreads();
    float sd2 = 0.f;
    #pragma unroll
    for (int half = 0; half < 2; half++) {
        int n = tid + half * 512;
        float D = 0.f;
        #pragma unroll
        for (int a = 0; a < Ac; a++) {
            float d = dist[(size_t)sloc[a] * Nc + n];
            D += d;
            sd2 = fmaf(d, d, sd2);
        }
        g_D[b * Nc + n] = D;
    }
    // reduce sd2 over block
    #pragma unroll
    for (int o = 16; o; o >>= 1) sd2 += __shfl_xor_sync(0xffffffffu, sd2, o);
    if ((tid & 31) == 0) rsd[tid >> 5] = sd2;
    __syncthreads();
    if (tid < 16) {
        float v = rsd[tid];
        #pragma unroll
        for (int o = 8; o; o >>= 1) v += __shfl_xor_sync(0x0000ffffu, v, o);
        if (tid == 0) g_sd2p[b] = v;
    }
    // Da: warp a (first 16 warps)
    int w = tid >> 5, lane = tid & 31;
    if (w < Ac) {
        const float* row = dist + (size_t)sloc[w] * Nc;
        float s = 0.f;
        for (int n = lane; n < Nc; n += 32) s += row[n];
        #pragma unroll
        for (int o = 16; o; o >>= 1) s += __shfl_xor_sync(0xffffffffu, s, o);
        if (lane == 0) g_Da[b * Ac + w] = s;
    }
}

// ================= stats sweep over node_proj =================
__global__ void __launch_bounds__(256) k_stats2() {
    int blk = blockIdx.x;
    int base = blk * 128;
    int tid = threadIdx.x;
    __shared__ float sD[128];
    if (tid < 128) sD[tid] = g_D[base + tid];
    __syncthreads();
    if (tid >= MIDc) return;
    int m = tid;
    float s1 = 0.f, s2 = 0.f, sd = 0.f;
    for (int r = 0; r < 128; r++) {
        float u = g_np[(size_t)(base + r) * MIDc + m];
        s1 += u;
        s2 = fmaf(u, u, s2);
        sd = fmaf(u, sD[r], sd);
    }
    g_p2[(size_t)blk * 3 * MIDc + m]            = s1;
    g_p2[(size_t)blk * 3 * MIDc + MIDc + m]     = s2;
    g_p2[(size_t)blk * 3 * MIDc + 2 * MIDc + m] = sd;
}

// ================= closed-form BN reduce =================
__global__ void __launch_bounds__(256) k_reduce2(const float* __restrict__ bn_g,
                                                 const float* __restrict__ bn_b) {
    int tid = threadIdx.x;
    __shared__ float sDa[Bc * Ac];
    for (int i = tid; i < Bc * Ac; i += 256) sDa[i] = g_Da[i];
    __syncthreads();
    if (tid >= MIDc) return;
    int m = tid;
    double SD = 0.0, SD2 = 0.0;
    for (int i = 0; i < Bc * Ac; i++) SD += (double)sDa[i];
    for (int b = 0; b < Bc; b++) SD2 += (double)g_sd2p[b];
    double c_ = (double)g_cb[m], e = (double)g_ewp[m];
    double S1np = 0.0, S2np = 0.0, SnpD = 0.0, cross = 0.0;
    double S1v = 0.0, S2v = 0.0, SvDa = 0.0;
    for (int b = 0; b < Bc; b++) {
        double s1b = 0.0;
        for (int c = 0; c < 8; c++) {
            int ch = b * 8 + c;
            s1b  += (double)g_p2[(size_t)ch * 3 * MIDc + m];
            S2np += (double)g_p2[(size_t)ch * 3 * MIDc + MIDc + m];
            SnpD += (double)g_p2[(size_t)ch * 3 * MIDc + 2 * MIDc + m];
        }
        double s1vb = 0.0;
        for (int a = 0; a < Ac; a++) {
            double v = (double)g_pre1[(size_t)(b * Ac + a) * MIDc + m];
            s1vb += v;
            S2v  += v * v;
            SvDa += v * (double)sDa[b * Ac + a];
        }
        S1np += s1b;
        S1v  += s1vb;
        cross += (s1b + (double)Nc * c_) * s1vb;
    }
    double S1u = S1np + (double)NODES * c_;
    double S2u = S2np + 2.0 * c_ * S1np + (double)NODES * c_ * c_;
    double SuD = SnpD + c_ * SD;
    double s1 = (double)Ac * S1u + (double)Nc * S1v + e * SD;
    double s2 = (double)Ac * S2u + (double)Nc * S2v + e * e * SD2
              + 2.0 * cross + 2.0 * e * SuD + 2.0 * e * SvDa;
    double inv = 1.0 / (double)ROWSc;
    double mu = s1 * inv;
    double var = s2 * inv - mu * mu;
    float al = bn_g[m] * (float)rsqrt(var + 1e-5);
    g_alpha[m] = al;
    g_beta[m]  = bn_b[m] - (float)mu * al;
}

// ================= final logits =================
__global__ void __launch_bounds__(512) k_final(const int* __restrict__ loc,
                                               const float* __restrict__ dist,
                                               const float* __restrict__ W2,
                                               const float* __restrict__ b2,
                                               const int* __restrict__ mask) {
    int chunk = blockIdx.x;
    int p0 = chunk * 16;
    int b = p0 >> 10;
    int tid = threadIdx.x;
    int a = tid >> 5, lane = tid & 31;
    __shared__ float sp[Ac * MIDc];
    __shared__ float snp[16][MIDc];
    __shared__ float sal[MIDc], sbe[MIDc], sw2[MIDc], sewp[MIDc], scb[MIDc];
    __shared__ float sd[16][Ac];
    __shared__ int sloc[Ac];
    for (int i = tid; i < Ac * MIDc; i += 512) sp[i] = g_pre1[(size_t)b * Ac * MIDc + i];
    for (int i = tid; i < 16 * MIDc; i += 512) {
        int r = i / MIDc, c = i - r * MIDc;
        snp[r][c] = g_np[(size_t)(p0 + r) * MIDc + c];
    }
    if (tid < MIDc) {
        sal[tid] = g_alpha[tid]; sbe[tid] = g_beta[tid];
        sw2[tid] = W2[tid]; sewp[tid] = g_ewp[tid]; scb[tid] = g_cb[tid];
    }
    if (tid < Ac) sloc[tid] = loc[b * Ac + tid];
    __syncthreads();
    for (int i = tid; i < 16 * Ac; i += 512) {
        int r = i >> 4, aa = i & 15;
        int n = (p0 + r) & 1023;
        sd[r][aa] = dist[(size_t)sloc[aa] * Nc + n];
    }
    __syncthreads();
    float bb2 = b2[0];
    for (int ii = 0; ii < 16; ii++) {
        int n = (p0 + ii) & 1023;
        float d = sd[ii][a];
        float part = 0.f;
        for (int m = lane; m < MIDc; m += 32) {
            float h = snp[ii][m] + sp[a * MIDc + m] + d * sewp[m] + scb[m];
            float y = fmaxf(fmaf(sal[m], h, sbe[m]), 0.f);
            part = fmaf(y, sw2[m], part);
        }
        #pragma unroll
        for (int o = 16; o; o >>= 1) part += __shfl_xor_sync(0xffffffffu, part, o);
        if (lane == 0) {
            int ridx = b * (Ac * Nc) + a * Nc + n;
            g_logits[ridx] = (mask[ridx] != 0) ? (part + bb2) : -1e8f;
        }
    }
}

// ================= softmax per batch =================
__global__ void __launch_bounds__(1024) k_softmax(float* __restrict__ out) {
    int b = blockIdx.x, tid = threadIdx.x;
    const float* L = g_logits + (size_t)b * Ac * Nc;
    __shared__ float red[32];
    __shared__ float sval;
    float mx = -3.4028235e38f;
    for (int i = tid; i < Ac * Nc; i += 1024) mx = fmaxf(mx, L[i]);
    #pragma unroll
    for (int o = 16; o; o >>= 1) mx = fmaxf(mx, __shfl_xor_sync(0xffffffffu, mx, o));
    if ((tid & 31) == 0) red[tid >> 5] = mx;
    __syncthreads();
    if (tid < 32) {
        float v = red[tid];
        #pragma unroll
        for (int o = 16; o; o >>= 1) v = fmaxf(v, __shfl_xor_sync(0xffffffffu, v, o));
        if (tid == 0) sval = v;
    }
    __syncthreads();
    mx = sval;
    float s = 0.f;
    for (int i = tid; i < Ac * Nc; i += 1024) s += expf(L[i] - mx);
    #pragma unroll
    for (int o = 16; o; o >>= 1) s += __shfl_xor_sync(0xffffffffu, s, o);
    __syncthreads();
    if ((tid & 31) == 0) red[tid >> 5] = s;
    __syncthreads();
    if (tid < 32) {
        float v = red[tid];
        #pragma unroll
        for (int o = 16; o; o >>= 1) v += __shfl_xor_sync(0xffffffffu, v, o);
        if (tid == 0) sval = v;
    }
    __syncthreads();
    float inv = 1.f / sval;
    for (int i = tid; i < Ac * Nc; i += 1024)
        out[(size_t)b * Ac * Nc + i] = expf(L[i] - mx) * inv;
}

// ---------------- launch ----------------
extern "C" void kernel_launch(void* const* d_in, const int* in_sizes, int n_in,
                              void* d_out, int out_size) {
    const float* gnodes = (const float*)d_in[0];
    const int*   links  = (const int*)d_in[1];
    const int*   loc    = (const int*)d_in[2];
    const int*   mask   = (const int*)d_in[3];
    const float* dist   = (const float*)d_in[4];
    const float* cW[3]  = {(const float*)d_in[5],  (const float*)d_in[9],  (const float*)d_in[13]};
    const float* cb_[3] = {(const float*)d_in[6],  (const float*)d_in[10], (const float*)d_in[14]};
    const float* cg[3]  = {(const float*)d_in[7],  (const float*)d_in[11], (const float*)d_in[15]};
    const float* cbe[3] = {(const float*)d_in[8],  (const float*)d_in[12], (const float*)d_in[16]};
    const float* eW  = (const float*)d_in[17];
    const float* eb  = (const float*)d_in[18];
    const float* W1  = (const float*)d_in[19];
    const float* b1  = (const float*)d_in[20];
    const float* bng = (const float*)d_in[21];
    const float* bnb = (const float*)d_in[22];
    const float* W2  = (const float*)d_in[23];
    const float* b2  = (const float*)d_in[24];
    float* out = (float*)d_out;

    // CSR build (edges fixed across layers)
    k_zero2<<<(NODES + 255) / 256, 256>>>();
    k_count<<<(NEDGE + 255) / 256, 256>>>(links);
    k_scan<<<Bc, 1024>>>();
    k_fill<<<(NEDGE + 255) / 256, 256>>>(links);

    // x0 -> xc[:,0:16]
    k_copy_x0<<<(NODES * FINc + 255) / 256, 256>>>(gnodes);

    // 3 fused conv layers (input pointers resolved on device from `layer`)
    k_conv<FINc><<<NODES / 32, 512>>>(gnodes, cW[0], cb_[0], cg[0], cbe[0], 0);
    k_conv<Hc>  <<<NODES / 32, 512>>>(gnodes, cW[1], cb_[1], cg[1], cbe[1], 1);
    k_conv<Hc>  <<<NODES / 32, 512>>>(gnodes, cW[2], cb_[2], cg[2], cbe[2], 2);

    // gather agent rows
    k_gather<<<(Bc * Ac * MIDc + 255) / 256, 256>>>(loc);

    // GEMMs: mode 1: pre1 = ag @ W1[0:208] ; mode 0: np = xc @ W1[208:416]
    {
        dim3 gp(2, (Bc * Ac) / GM);
        k_gemm208<<<gp, 256>>>(W1, 1);
        dim3 gn(2, NODES / GM);
        k_gemm208<<<gn, 256>>>(W1 + (size_t)MIDc * MIDc, 0);
    }

    // edge projection + dist sums
    k_ewp<<<1, 256>>>(eW, eb, W1, b1);
    k_dsums<<<Bc, 512>>>(loc, dist);

    // BN stats: sweep + closed-form reduce
    k_stats2<<<NSCHUNK, 256>>>();
    k_reduce2<<<1, 256>>>(bng, bnb);

    // final logits + softmax
    k_final<<<NFCHUNK, 512>>>(loc, dist, W2, b2, mask);
    k_softmax<<<Bc, 1024>>>(out);
}

// round 10
// speedup vs baseline: 2.4775x; 1.8194x over previous
#include <cuda_runtime.h>
#include <cuda_bf16.h>
#include <cstdint>

// ---------------- problem constants ----------------
#define Bc    32
#define Nc    1024
#define Ac    16
#define Ec    4096
#define FINc  16
#define Hc    64
#define MIDc  208          // F_IN + 3*H
#define NODES 32768        // B*N
#define ROWSc 524288       // B*A*N
#define NEDGE 131072       // B*E
#define NFCHUNK 2048       // final chunks (16 nodes each)
#define NSCHUNK 256        // stats chunks (128 nodes each)

// ---------------- scratch (device globals; referenced ONLY from device code) --
__device__ float g_xc[NODES * MIDc];
__device__ float g_np[NODES * MIDc];
__device__ float g_ag[Bc * Ac * MIDc];
__device__ float g_pre1[Bc * Ac * MIDc];
__device__ float g_ewp[MIDc];
__device__ float g_cb[MIDc];
__device__ float g_alpha[MIDc];
__device__ float g_beta[MIDc];
__device__ float g_logits[ROWSc];
// CSR
__device__ int   g_cnt[NODES];
__device__ int   g_fill[NODES];
__device__ int   g_rowptr[NODES + 1];
__device__ int   g_col[NEDGE];
// closed-form BN stats
__device__ float g_D[NODES];
__device__ float g_Da[Bc * Ac];
__device__ float g_sd2p[Bc];
__device__ float g_p2[NSCHUNK * 3 * MIDc];
// W bf16 hi/lo planes, [slice][n][k-pair] linear; K padded 208->256 (kp 0..127)
__device__ unsigned int g_Bh[2 * MIDc * 128];
__device__ unsigned int g_Bl[2 * MIDc * 128];

// ================= CSR build =================
__global__ void k_zero2() {
    int i = blockIdx.x * blockDim.x + threadIdx.x;
    if (i < NODES) { g_cnt[i] = 0; g_fill[i] = 0; }
}
__global__ void k_count(const int* __restrict__ links) {
    int i = blockIdx.x * blockDim.x + threadIdx.x;
    if (i >= NEDGE) return;
    int b = i >> 12, e = i & 4095;
    int dst = links[b * 2 * Ec + Ec + e];
    atomicAdd(&g_cnt[b * Nc + dst], 1);
}
__global__ void __launch_bounds__(1024) k_scan() {
    int b = blockIdx.x, t = threadIdx.x;
    __shared__ int s[1024];
    int v = g_cnt[b * Nc + t];
    s[t] = v;
    __syncthreads();
    for (int off = 1; off < 1024; off <<= 1) {
        int x = (t >= off) ? s[t - off] : 0;
        __syncthreads();
        s[t] += x;
        __syncthreads();
    }
    g_rowptr[b * Nc + t] = b * Ec + s[t] - v;
    if (b == Bc - 1 && t == 1023) g_rowptr[NODES] = NEDGE;
}
__global__ void k_fill(const int* __restrict__ links) {
    int i = blockIdx.x * blockDim.x + threadIdx.x;
    if (i >= NEDGE) return;
    int b = i >> 12, e = i & 4095;
    int src = links[b * 2 * Ec + e];
    int dst = links[b * 2 * Ec + Ec + e];
    int node = b * Nc + dst;
    int pos = g_rowptr[node] + atomicAdd(&g_fill[node], 1);
    g_col[pos] = b * Nc + src;
}

// ================= W -> bf16 hi/lo planes, B^T layout [n][kpair] =========
// slice s uses W1 rows [s*208, s*208+208): B[n][k] = W1[s*208+k][n]
__global__ void k_prepW(const float* __restrict__ W1) {
    int i = blockIdx.x * blockDim.x + threadIdx.x;
    if (i >= 2 * MIDc * 128) return;
    int s = i / (MIDc * 128);
    int rem = i - s * (MIDc * 128);
    int n  = rem >> 7;          // 0..207
    int kp = rem & 127;         // k pair 0..127
    int k0 = 2 * kp;
    float w0 = (k0     < MIDc) ? W1[(size_t)(s * MIDc + k0)     * MIDc + n] : 0.f;
    float w1 = (k0 + 1 < MIDc) ? W1[(size_t)(s * MIDc + k0 + 1) * MIDc + n] : 0.f;
    __nv_bfloat16 h0 = __float2bfloat16(w0), h1 = __float2bfloat16(w1);
    __nv_bfloat16 l0 = __float2bfloat16(w0 - __bfloat162float(h0));
    __nv_bfloat16 l1 = __float2bfloat16(w1 - __bfloat162float(h1));
    uint32_t hi = (uint32_t)__bfloat16_as_ushort(h0) | ((uint32_t)__bfloat16_as_ushort(h1) << 16);
    uint32_t lo = (uint32_t)__bfloat16_as_ushort(l0) | ((uint32_t)__bfloat16_as_ushort(l1) << 16);
    g_Bh[i] = hi;
    g_Bl[i] = lo;
}

// ================= fused conv (gather-agg + MLP + LN + ReLU) =================
template <int F>
__global__ void __launch_bounds__(512) k_conv(const float* __restrict__ gnodes,
                                              const float* __restrict__ W,
                                              const float* __restrict__ bias,
                                              const float* __restrict__ gg,
                                              const float* __restrict__ beta,
                                              int layer) {
    const float* X;
    int xs, outOff;
    if (layer == 0)      { X = gnodes;    xs = FINc; outOff = 16; }
    else if (layer == 1) { X = g_xc + 16; xs = MIDc; outOff = 80; }
    else                 { X = g_xc + 80; xs = MIDc; outOff = 144; }

    int tid = threadIdx.x;
    int h = tid & 63, tg = tid >> 6;
    int base = blockIdx.x * 32;
    __shared__ float sW[F * 64];
    __shared__ float sagg[32][64];
    __shared__ float sbias[64], sg[64], sb[64];
    __shared__ float red1[8][2][4], red2[8][2][4];
    // fold x0 copy into layer 0
    if (layer == 0) {
        int node = base + (tid >> 4);
        g_xc[(size_t)node * MIDc + (tid & 15)] = gnodes[(size_t)node * FINc + (tid & 15)];
    }
    for (int i = tid; i < F * 64; i += 512) sW[i] = W[i];
    if (tid < 64) { sbias[tid] = bias[tid]; sg[tid] = gg[tid]; sb[tid] = beta[tid]; }
    if (h < F) {
        #pragma unroll
        for (int j = 0; j < 4; j++) {
            int node = base + tg * 4 + j;
            int p0 = g_rowptr[node], p1 = g_rowptr[node + 1];
            float s = 0.f;
            for (int p = p0; p < p1; p++) s += X[(size_t)g_col[p] * xs + h];
            sagg[tg * 4 + j][h] = s;
        }
    }
    __syncthreads();
    float acc[4];
    #pragma unroll
    for (int j = 0; j < 4; j++) acc[j] = sbias[h];
    #pragma unroll
    for (int f = 0; f < F; f += 4) {
        float w0 = sW[(f + 0) * 64 + h];
        float w1 = sW[(f + 1) * 64 + h];
        float w2 = sW[(f + 2) * 64 + h];
        float w3 = sW[(f + 3) * 64 + h];
        #pragma unroll
        for (int j = 0; j < 4; j++) {
            float4 a = *reinterpret_cast<const float4*>(&sagg[tg * 4 + j][f]);
            acc[j] = fmaf(a.x, w0, acc[j]);
            acc[j] = fmaf(a.y, w1, acc[j]);
            acc[j] = fmaf(a.z, w2, acc[j]);
            acc[j] = fmaf(a.w, w3, acc[j]);
        }
    }
    float v1[4], v2[4];
    #pragma unroll
    for (int j = 0; j < 4; j++) { v1[j] = acc[j]; v2[j] = acc[j] * acc[j]; }
    #pragma unroll
    for (int o = 16; o; o >>= 1) {
        #pragma unroll
        for (int j = 0; j < 4; j++) {
            v1[j] += __shfl_xor_sync(0xffffffffu, v1[j], o);
            v2[j] += __shfl_xor_sync(0xffffffffu, v2[j], o);
        }
    }
    int wh = h >> 5;
    if ((h & 31) == 0) {
        #pragma unroll
        for (int j = 0; j < 4; j++) { red1[tg][wh][j] = v1[j]; red2[tg][wh][j] = v2[j]; }
    }
    __syncthreads();
    #pragma unroll
    for (int j = 0; j < 4; j++) {
        float sum = red1[tg][0][j] + red1[tg][1][j];
        float sq  = red2[tg][0][j] + red2[tg][1][j];
        float mean = sum * (1.f / 64.f);
        float var  = sq * (1.f / 64.f) - mean * mean;
        float y = (acc[j] - mean) * rsqrtf(var + 1e-5f) * sg[h] + sb[h];
        int node = base + tg * 4 + j;
        g_xc[(size_t)node * MIDc + outOff + h] = fmaxf(y, 0.f);
    }
}

// ================= gather agent rows =================
__global__ void k_gather(const int* __restrict__ loc) {
    int i = blockIdx.x * blockDim.x + threadIdx.x;
    if (i >= Bc * Ac * MIDc) return;
    int r = i / MIDc, k = i - r * MIDc;
    int b = r >> 4;
    int node = b * Nc + loc[r];
    g_ag[i] = g_xc[(size_t)node * MIDc + k];
}

// ========== tensor GEMM via mma.sync bf16 (3-term compensated) ==========
// C[M,208] = A[M,208] @ Wslice.  mode 0: A=g_xc,C=g_np,slice1 ; mode 1: ag->pre1,slice0
// CTA: 256 thr (8 warps). CTA tile 128x208; warp w: rows 16w..16w+15 x 208 cols.
// K chunked 64 (4 chunks; last has 1 valid kstep of 16).
#define SA_H 0
#define SA_L 16896
#define SB_H 33792
#define SB_L 61248
#define TG_SMEM 88704

__device__ __forceinline__ void mma16816(float* c, uint32_t a0, uint32_t a1,
                                         uint32_t a2, uint32_t a3,
                                         uint32_t b0, uint32_t b1) {
    asm volatile(
        "mma.sync.aligned.m16n8k16.row.col.f32.bf16.bf16.f32 "
        "{%0,%1,%2,%3}, {%4,%5,%6,%7}, {%8,%9}, {%0,%1,%2,%3};"
        : "+f"(c[0]), "+f"(c[1]), "+f"(c[2]), "+f"(c[3])
        : "r"(a0), "r"(a1), "r"(a2), "r"(a3), "r"(b0), "r"(b1));
}

__global__ void __launch_bounds__(256, 1) k_tgemm(int mode) {
    const float* A = mode ? g_ag : g_xc;
    float* C       = mode ? g_pre1 : g_np;
    int slice      = mode ? 0 : 1;

    extern __shared__ char smem[];
    uint32_t* sAh = reinterpret_cast<uint32_t*>(smem + SA_H);  // [128][33]
    uint32_t* sAl = reinterpret_cast<uint32_t*>(smem + SA_L);
    uint32_t* sBh = reinterpret_cast<uint32_t*>(smem + SB_H);  // [208][33]
    uint32_t* sBl = reinterpret_cast<uint32_t*>(smem + SB_L);

    int tid = threadIdx.x;
    int wid = tid >> 5, lane = tid & 31;
    int gid = lane >> 2, tig = lane & 3;
    int bm = blockIdx.x * 128;
    int m0 = wid * 16;
    const uint32_t* Bh = g_Bh + slice * (MIDc * 128);
    const uint32_t* Bl = g_Bl + slice * (MIDc * 128);

    float acc[26][4];
    #pragma unroll
    for (int j = 0; j < 26; j++)
        #pragma unroll
        for (int q = 0; q < 4; q++) acc[j][q] = 0.f;

    for (int c = 0; c < 4; c++) {
        // A chunk: 128 rows x 32 k-words; fp32 -> bf16 hi/lo
        #pragma unroll
        for (int t = 0; t < 16; t++) {
            int i = tid + t * 256;
            int row = i >> 5, w = i & 31;
            int gk = c * 64 + 2 * w;
            float a0 = 0.f, a1 = 0.f;
            if (gk < MIDc) {
                float2 v = *reinterpret_cast<const float2*>(&A[(size_t)(bm + row) * MIDc + gk]);
                a0 = v.x; a1 = v.y;
            }
            __nv_bfloat16 h0 = __float2bfloat16(a0), h1 = __float2bfloat16(a1);
            __nv_bfloat16 l0 = __float2bfloat16(a0 - __bfloat162float(h0));
            __nv_bfloat16 l1 = __float2bfloat16(a1 - __bfloat162float(h1));
            sAh[row * 33 + w] = (uint32_t)__bfloat16_as_ushort(h0) | ((uint32_t)__bfloat16_as_ushort(h1) << 16);
            sAl[row * 33 + w] = (uint32_t)__bfloat16_as_ushort(l0) | ((uint32_t)__bfloat16_as_ushort(l1) << 16);
        }
        // B chunk: 208 rows x 32 k-words (pre-split)
        #pragma unroll
        for (int t = 0; t < 26; t++) {
            int i = tid + t * 256;
            int n = i >> 5, w = i & 31;
            sBh[n * 33 + w] = Bh[n * 128 + c * 32 + w];
            sBl[n * 33 + w] = Bl[n * 128 + c * 32 + w];
        }
        __syncthreads();

        int nks = (c < 3) ? 4 : 1;   // chunk 3: only k=192..207 valid
        for (int ks = 0; ks < nks; ks++) {
            int kb = ks * 8;
            int ra = (m0 + gid) * 33 + kb + tig;
            uint32_t ah0 = sAh[ra],       ah1 = sAh[ra + 264];
            uint32_t ah2 = sAh[ra + 4],   ah3 = sAh[ra + 268];
            uint32_t al0 = sAl[ra],       al1 = sAl[ra + 264];
            uint32_t al2 = sAl[ra + 4],   al3 = sAl[ra + 268];
            #pragma unroll
            for (int j = 0; j < 26; j++) {
                int rb = (j * 8 + gid) * 33 + kb + tig;
                uint32_t bh0 = sBh[rb], bh1 = sBh[rb + 4];
                uint32_t bl0 = sBl[rb], bl1 = sBl[rb + 4];
                mma16816(acc[j], ah0, ah1, ah2, ah3, bh0, bh1);
                mma16816(acc[j], al0, al1, al2, al3, bh0, bh1);
                mma16816(acc[j], ah0, ah1, ah2, ah3, bl0, bl1);
            }
        }
        __syncthreads();
    }

    // epilogue: c0,c1 -> row r0 cols n0,n0+1 ; c2,c3 -> row r0+8
    int r0 = bm + m0 + gid, r1 = r0 + 8;
    #pragma unroll
    for (int j = 0; j < 26; j++) {
        int n0 = j * 8 + 2 * tig;
        *reinterpret_cast<float2*>(&C[(size_t)r0 * MIDc + n0]) = make_float2(acc[j][0], acc[j][1]);
        *reinterpret_cast<float2*>(&C[(size_t)r1 * MIDc + n0]) = make_float2(acc[j][2], acc[j][3]);
    }
}

// ================= edge projection =================
__global__ void k_ewp(const float* __restrict__ eW, const float* __restrict__ eb,
                      const float* __restrict__ W1, const float* __restrict__ b1) {
    int m = threadIdx.x;
    if (m >= MIDc) return;
    float s = 0.f, t = 0.f;
    #pragma unroll 8
    for (int h2 = 0; h2 < Hc; h2++) {
        float w = W1[(size_t)(2 * MIDc + h2) * MIDc + m];
        s = fmaf(eW[h2], w, s);
        t = fmaf(eb[h2], w, t);
    }
    g_ewp[m] = s;
    g_cb[m]  = t + b1[m];
}

// ================= dist row/col sums =================
__global__ void __launch_bounds__(512) k_dsums(const int* __restrict__ loc,
                                               const float* __restrict__ dist) {
    int b = blockIdx.x, tid = threadIdx.x;
    __shared__ int sloc[Ac];
    __shared__ float rsd[16];
    if (tid < Ac) sloc[tid] = loc[b * Ac + tid];
    __syncthreads();
    float sd2 = 0.f;
    #pragma unroll
    for (int half = 0; half < 2; half++) {
        int n = tid + half * 512;
        float D = 0.f;
        #pragma unroll
        for (int a = 0; a < Ac; a++) {
            float d = dist[(size_t)sloc[a] * Nc + n];
            D += d;
            sd2 = fmaf(d, d, sd2);
        }
        g_D[b * Nc + n] = D;
    }
    #pragma unroll
    for (int o = 16; o; o >>= 1) sd2 += __shfl_xor_sync(0xffffffffu, sd2, o);
    if ((tid & 31) == 0) rsd[tid >> 5] = sd2;
    __syncthreads();
    if (tid < 16) {
        float v = rsd[tid];
        #pragma unroll
        for (int o = 8; o; o >>= 1) v += __shfl_xor_sync(0x0000ffffu, v, o);
        if (tid == 0) g_sd2p[b] = v;
    }
    int w = tid >> 5, lane = tid & 31;
    if (w < Ac) {
        const float* row = dist + (size_t)sloc[w] * Nc;
        float s = 0.f;
        for (int n = lane; n < Nc; n += 32) s += row[n];
        #pragma unroll
        for (int o = 16; o; o >>= 1) s += __shfl_xor_sync(0xffffffffu, s, o);
        if (lane == 0) g_Da[b * Ac + w] = s;
    }
}

// ================= stats sweep over node_proj =================
__global__ void __launch_bounds__(256) k_stats2() {
    int blk = blockIdx.x;
    int base = blk * 128;
    int tid = threadIdx.x;
    __shared__ float sD[128];
    if (tid < 128) sD[tid] = g_D[base + tid];
    __syncthreads();
    if (tid >= MIDc) return;
    int m = tid;
    float s1 = 0.f, s2 = 0.f, sd = 0.f;
    for (int r = 0; r < 128; r++) {
        float u = g_np[(size_t)(base + r) * MIDc + m];
        s1 += u;
        s2 = fmaf(u, u, s2);
        sd = fmaf(u, sD[r], sd);
    }
    g_p2[(size_t)blk * 3 * MIDc + m]            = s1;
    g_p2[(size_t)blk * 3 * MIDc + MIDc + m]     = s2;
    g_p2[(size_t)blk * 3 * MIDc + 2 * MIDc + m] = sd;
}

// ================= closed-form BN reduce =================
__global__ void __launch_bounds__(256) k_reduce2(const float* __restrict__ bn_g,
                                                 const float* __restrict__ bn_b) {
    int tid = threadIdx.x;
    __shared__ float sDa[Bc * Ac];
    for (int i = tid; i < Bc * Ac; i += 256) sDa[i] = g_Da[i];
    __syncthreads();
    if (tid >= MIDc) return;
    int m = tid;
    float SD = 0.f, SD2 = 0.f;
    for (int i = 0; i < Bc * Ac; i++) SD += sDa[i];
    for (int b = 0; b < Bc; b++) SD2 += g_sd2p[b];
    double c_ = (double)g_cb[m], e = (double)g_ewp[m];
    float S2np = 0.f, SnpD = 0.f, S2v = 0.f, SvDa = 0.f;
    double S1np = 0.0, S1v = 0.0, cross = 0.0;
    for (int b = 0; b < Bc; b++) {
        float s1b = 0.f;
        for (int c = 0; c < 8; c++) {
            int ch = b * 8 + c;
            s1b  += g_p2[(size_t)ch * 3 * MIDc + m];
            S2np += g_p2[(size_t)ch * 3 * MIDc + MIDc + m];
            SnpD += g_p2[(size_t)ch * 3 * MIDc + 2 * MIDc + m];
        }
        float s1vb = 0.f;
        for (int a = 0; a < Ac; a++) {
            float v = g_pre1[(size_t)(b * Ac + a) * MIDc + m];
            s1vb += v;
            S2v  = fmaf(v, v, S2v);
            SvDa = fmaf(v, sDa[b * Ac + a], SvDa);
        }
        S1np += (double)s1b;
        S1v  += (double)s1vb;
        cross += ((double)s1b + (double)Nc * c_) * (double)s1vb;
    }
    double S1u = S1np + (double)NODES * c_;
    double S2u = (double)S2np + 2.0 * c_ * S1np + (double)NODES * c_ * c_;
    double SuD = (double)SnpD + c_ * (double)SD;
    double s1 = (double)Ac * S1u + (double)Nc * S1v + e * (double)SD;
    double s2 = (double)Ac * S2u + (double)Nc * (double)S2v + e * e * (double)SD2
              + 2.0 * cross + 2.0 * e * SuD + 2.0 * e * (double)SvDa;
    double inv = 1.0 / (double)ROWSc;
    double mu = s1 * inv;
    double var = s2 * inv - mu * mu;
    float al = bn_g[m] * (float)rsqrt(var + 1e-5);
    g_alpha[m] = al;
    g_beta[m]  = bn_b[m] - (float)mu * al;
}

// ================= final logits =================
__global__ void __launch_bounds__(512) k_final(const int* __restrict__ loc,
                                               const float* __restrict__ dist,
                                               const float* __restrict__ W2,
                                               const float* __restrict__ b2,
                                               const int* __restrict__ mask) {
    int chunk = blockIdx.x;
    int p0 = chunk * 16;
    int b = p0 >> 10;
    int tid = threadIdx.x;
    int a = tid >> 5, lane = tid & 31;
    __shared__ float sp[Ac * MIDc];
    __shared__ float snp[16][MIDc];
    __shared__ float sal[MIDc], sbe[MIDc], sw2[MIDc], sewp[MIDc], scb[MIDc];
    __shared__ float sd[16][Ac];
    __shared__ int sloc[Ac];
    for (int i = tid; i < Ac * MIDc; i += 512) sp[i] = g_pre1[(size_t)b * Ac * MIDc + i];
    for (int i = tid; i < 16 * MIDc; i += 512) {
        int r = i / MIDc, c = i - r * MIDc;
        snp[r][c] = g_np[(size_t)(p0 + r) * MIDc + c];
    }
    if (tid < MIDc) {
        sal[tid] = g_alpha[tid]; sbe[tid] = g_beta[tid];
        sw2[tid] = W2[tid]; sewp[tid] = g_ewp[tid]; scb[tid] = g_cb[tid];
    }
    if (tid < Ac) sloc[tid] = loc[b * Ac + tid];
    __syncthreads();
    for (int i = tid; i < 16 * Ac; i += 512) {
        int r = i >> 4, aa = i & 15;
        int n = (p0 + r) & 1023;
        sd[r][aa] = dist[(size_t)sloc[aa] * Nc + n];
    }
    __syncthreads();
    float bb2 = b2[0];
    for (int ii = 0; ii < 16; ii++) {
        int n = (p0 + ii) & 1023;
        float d = sd[ii][a];
        float part = 0.f;
        for (int m = lane; m < MIDc; m += 32) {
            float h = snp[ii][m] + sp[a * MIDc + m] + d * sewp[m] + scb[m];
            float y = fmaxf(fmaf(sal[m], h, sbe[m]), 0.f);
            part = fmaf(y, sw2[m], part);
        }
        #pragma unroll
        for (int o = 16; o; o >>= 1) part += __shfl_xor_sync(0xffffffffu, part, o);
        if (lane == 0) {
            int ridx = b * (Ac * Nc) + a * Nc + n;
            g_logits[ridx] = (mask[ridx] != 0) ? (part + bb2) : -1e8f;
        }
    }
}

// ================= softmax per batch =================
__global__ void __launch_bounds__(1024) k_softmax(float* __restrict__ out) {
    int b = blockIdx.x, tid = threadIdx.x;
    const float* L = g_logits + (size_t)b * Ac * Nc;
    __shared__ float red[32];
    __shared__ float sval;
    float mx = -3.4028235e38f;
    for (int i = tid; i < Ac * Nc; i += 1024) mx = fmaxf(mx, L[i]);
    #pragma unroll
    for (int o = 16; o; o >>= 1) mx = fmaxf(mx, __shfl_xor_sync(0xffffffffu, mx, o));
    if ((tid & 31) == 0) red[tid >> 5] = mx;
    __syncthreads();
    if (tid < 32) {
        float v = red[tid];
        #pragma unroll
        for (int o = 16; o; o >>= 1) v = fmaxf(v, __shfl_xor_sync(0xffffffffu, v, o));
        if (tid == 0) sval = v;
    }
    __syncthreads();
    mx = sval;
    float s = 0.f;
    for (int i = tid; i < Ac * Nc; i += 1024) s += expf(L[i] - mx);
    #pragma unroll
    for (int o = 16; o; o >>= 1) s += __shfl_xor_sync(0xffffffffu, s, o);
    __syncthreads();
    if ((tid & 31) == 0) red[tid >> 5] = s;
    __syncthreads();
    if (tid < 32) {
        float v = red[tid];
        #pragma unroll
        for (int o = 16; o; o >>= 1) v += __shfl_xor_sync(0xffffffffu, v, o);
        if (tid == 0) sval = v;
    }
    __syncthreads();
    float inv = 1.f / sval;
    for (int i = tid; i < Ac * Nc; i += 1024)
        out[(size_t)b * Ac * Nc + i] = expf(L[i] - mx) * inv;
}

// ---------------- launch ----------------
extern "C" void kernel_launch(void* const* d_in, const int* in_sizes, int n_in,
                              void* d_out, int out_size) {
    const float* gnodes = (const float*)d_in[0];
    const int*   links  = (const int*)d_in[1];
    const int*   loc    = (const int*)d_in[2];
    const int*   mask   = (const int*)d_in[3];
    const float* dist   = (const float*)d_in[4];
    const float* cW[3]  = {(const float*)d_in[5],  (const float*)d_in[9],  (const float*)d_in[13]};
    const float* cb_[3] = {(const float*)d_in[6],  (const float*)d_in[10], (const float*)d_in[14]};
    const float* cg[3]  = {(const float*)d_in[7],  (const float*)d_in[11], (const float*)d_in[15]};
    const float* cbe[3] = {(const float*)d_in[8],  (const float*)d_in[12], (const float*)d_in[16]};
    const float* eW  = (const float*)d_in[17];
    const float* eb  = (const float*)d_in[18];
    const float* W1  = (const float*)d_in[19];
    const float* b1  = (const float*)d_in[20];
    const float* bng = (const float*)d_in[21];
    const float* bnb = (const float*)d_in[22];
    const float* W2  = (const float*)d_in[23];
    const float* b2  = (const float*)d_in[24];
    float* out = (float*)d_out;

    cudaFuncSetAttribute(k_tgemm, cudaFuncAttributeMaxDynamicSharedMemorySize, TG_SMEM);

    // CSR build
    k_zero2<<<(NODES + 255) / 256, 256>>>();
    k_count<<<(NEDGE + 255) / 256, 256>>>(links);
    k_scan<<<Bc, 1024>>>();
    k_fill<<<(NEDGE + 255) / 256, 256>>>(links);

    // W hi/lo planes (both actor1 slices), B^T linear layout
    k_prepW<<<(2 * MIDc * 128 + 255) / 256, 256>>>(W1);

    // fused conv layers (layer 0 also copies x0 into xc)
    k_conv<FINc><<<NODES / 32, 512>>>(gnodes, cW[0], cb_[0], cg[0], cbe[0], 0);
    k_conv<Hc>  <<<NODES / 32, 512>>>(gnodes, cW[1], cb_[1], cg[1], cbe[1], 1);
    k_conv<Hc>  <<<NODES / 32, 512>>>(gnodes, cW[2], cb_[2], cg[2], cbe[2], 2);

    // gather agent rows
    k_gather<<<(Bc * Ac * MIDc + 255) / 256, 256>>>(loc);

    // tensor-core GEMMs: pre1 (512 rows, slice 0), np (32768 rows, slice 1)
    k_tgemm<<<(Bc * Ac) / 128, 256, TG_SMEM>>>(1);
    k_tgemm<<<NODES / 128, 256, TG_SMEM>>>(0);

    // edge projection + dist sums
    k_ewp<<<1, 256>>>(eW, eb, W1, b1);
    k_dsums<<<Bc, 512>>>(loc, dist);

    // BN stats
    k_stats2<<<NSCHUNK, 256>>>();
    k_reduce2<<<1, 256>>>(bng, bnb);

    // final logits + softmax
    k_final<<<NFCHUNK, 512>>>(loc, dist, W2, b2, mask);
    k_softmax<<<Bc, 1024>>>(out);
}

// round 11
// speedup vs baseline: 2.9860x; 1.2053x over previous
#include <cuda_runtime.h>
#include <cuda_bf16.h>
#include <cstdint>

// ---------------- problem constants ----------------
#define Bc    32
#define Nc    1024
#define Ac    16
#define Ec    4096
#define FINc  16
#define Hc    64
#define MIDc  208          // F_IN + 3*H
#define NODES 32768        // B*N
#define ROWSc 524288       // B*A*N
#define NEDGE 131072       // B*E
#define NFCHUNK 2048       // final chunks (16 nodes each)
#define NSCHUNK 256        // stats chunks (128 nodes each)

// ---------------- scratch (device globals; referenced ONLY from device code) --
__device__ float g_xc[NODES * MIDc];
__device__ float g_np[NODES * MIDc];
__device__ float g_ag[Bc * Ac * MIDc];
__device__ float g_pre1[Bc * Ac * MIDc];
__device__ float g_ewp[MIDc];
__device__ float g_cb[MIDc];
__device__ float g_alpha[MIDc];
__device__ float g_beta[MIDc];
__device__ float g_logits[ROWSc];
// CSR
__device__ int   g_cnt[NODES];
__device__ int   g_fill[NODES];
__device__ int   g_rowptr[NODES + 1];
__device__ int   g_col[NEDGE];
// closed-form BN stats
__device__ float g_D[NODES];
__device__ float g_Da[Bc * Ac];
__device__ float g_sd2p[Bc];
__device__ float g_p2[NSCHUNK * 3 * MIDc];
// softmax partials: (max, sumexp) per 2048-slice
__device__ float g_smx[Bc * 8 * 2];
// W bf16 hi/lo planes, [slice][n][k-pair] linear; K padded 208->256 (kp 0..127)
__device__ unsigned int g_Bh[2 * MIDc * 128];
__device__ unsigned int g_Bl[2 * MIDc * 128];

// ================= CSR build =================
__global__ void k_zero2() {
    int i = blockIdx.x * blockDim.x + threadIdx.x;
    if (i < NODES) { g_cnt[i] = 0; g_fill[i] = 0; }
}
__global__ void k_count(const int* __restrict__ links) {
    int i = blockIdx.x * blockDim.x + threadIdx.x;
    if (i >= NEDGE) return;
    int b = i >> 12, e = i & 4095;
    int dst = links[b * 2 * Ec + Ec + e];
    atomicAdd(&g_cnt[b * Nc + dst], 1);
}
__global__ void __launch_bounds__(1024) k_scan() {
    int b = blockIdx.x, t = threadIdx.x;
    __shared__ int s[1024];
    int v = g_cnt[b * Nc + t];
    s[t] = v;
    __syncthreads();
    for (int off = 1; off < 1024; off <<= 1) {
        int x = (t >= off) ? s[t - off] : 0;
        __syncthreads();
        s[t] += x;
        __syncthreads();
    }
    g_rowptr[b * Nc + t] = b * Ec + s[t] - v;
    if (b == Bc - 1 && t == 1023) g_rowptr[NODES] = NEDGE;
}
__global__ void k_fill(const int* __restrict__ links) {
    int i = blockIdx.x * blockDim.x + threadIdx.x;
    if (i >= NEDGE) return;
    int b = i >> 12, e = i & 4095;
    int src = links[b * 2 * Ec + e];
    int dst = links[b * 2 * Ec + Ec + e];
    int node = b * Nc + dst;
    int pos = g_rowptr[node] + atomicAdd(&g_fill[node], 1);
    g_col[pos] = b * Nc + src;
}

// ================= W -> bf16 hi/lo planes, B^T layout [n][kpair] =========
__global__ void k_prepW(const float* __restrict__ W1) {
    int i = blockIdx.x * blockDim.x + threadIdx.x;
    if (i >= 2 * MIDc * 128) return;
    int s = i / (MIDc * 128);
    int rem = i - s * (MIDc * 128);
    int n  = rem >> 7;
    int kp = rem & 127;
    int k0 = 2 * kp;
    float w0 = (k0     < MIDc) ? W1[(size_t)(s * MIDc + k0)     * MIDc + n] : 0.f;
    float w1 = (k0 + 1 < MIDc) ? W1[(size_t)(s * MIDc + k0 + 1) * MIDc + n] : 0.f;
    __nv_bfloat16 h0 = __float2bfloat16(w0), h1 = __float2bfloat16(w1);
    __nv_bfloat16 l0 = __float2bfloat16(w0 - __bfloat162float(h0));
    __nv_bfloat16 l1 = __float2bfloat16(w1 - __bfloat162float(h1));
    g_Bh[i] = (uint32_t)__bfloat16_as_ushort(h0) | ((uint32_t)__bfloat16_as_ushort(h1) << 16);
    g_Bl[i] = (uint32_t)__bfloat16_as_ushort(l0) | ((uint32_t)__bfloat16_as_ushort(l1) << 16);
}

// ================= fused conv (gather-agg + MLP + LN + ReLU) =================
template <int F>
__global__ void __launch_bounds__(512) k_conv(const float* __restrict__ gnodes,
                                              const float* __restrict__ W,
                                              const float* __restrict__ bias,
                                              const float* __restrict__ gg,
                                              const float* __restrict__ beta,
                                              int layer) {
    const float* X;
    int xs, outOff;
    if (layer == 0)      { X = gnodes;    xs = FINc; outOff = 16; }
    else if (layer == 1) { X = g_xc + 16; xs = MIDc; outOff = 80; }
    else                 { X = g_xc + 80; xs = MIDc; outOff = 144; }

    int tid = threadIdx.x;
    int h = tid & 63, tg = tid >> 6;
    int base = blockIdx.x * 32;
    __shared__ float sW[F * 64];
    __shared__ float sagg[32][64];
    __shared__ float sbias[64], sg[64], sb[64];
    __shared__ float red1[8][2][4], red2[8][2][4];
    if (layer == 0) {
        int node = base + (tid >> 4);
        g_xc[(size_t)node * MIDc + (tid & 15)] = gnodes[(size_t)node * FINc + (tid & 15)];
    }
    for (int i = tid; i < F * 64; i += 512) sW[i] = W[i];
    if (tid < 64) { sbias[tid] = bias[tid]; sg[tid] = gg[tid]; sb[tid] = beta[tid]; }
    if (h < F) {
        #pragma unroll
        for (int j = 0; j < 4; j++) {
            int node = base + tg * 4 + j;
            int p0 = g_rowptr[node], p1 = g_rowptr[node + 1];
            float s = 0.f;
            for (int p = p0; p < p1; p++) s += X[(size_t)g_col[p] * xs + h];
            sagg[tg * 4 + j][h] = s;
        }
    }
    __syncthreads();
    float acc[4];
    #pragma unroll
    for (int j = 0; j < 4; j++) acc[j] = sbias[h];
    #pragma unroll
    for (int f = 0; f < F; f += 4) {
        float w0 = sW[(f + 0) * 64 + h];
        float w1 = sW[(f + 1) * 64 + h];
        float w2 = sW[(f + 2) * 64 + h];
        float w3 = sW[(f + 3) * 64 + h];
        #pragma unroll
        for (int j = 0; j < 4; j++) {
            float4 a = *reinterpret_cast<const float4*>(&sagg[tg * 4 + j][f]);
            acc[j] = fmaf(a.x, w0, acc[j]);
            acc[j] = fmaf(a.y, w1, acc[j]);
            acc[j] = fmaf(a.z, w2, acc[j]);
            acc[j] = fmaf(a.w, w3, acc[j]);
        }
    }
    float v1[4], v2[4];
    #pragma unroll
    for (int j = 0; j < 4; j++) { v1[j] = acc[j]; v2[j] = acc[j] * acc[j]; }
    #pragma unroll
    for (int o = 16; o; o >>= 1) {
        #pragma unroll
        for (int j = 0; j < 4; j++) {
            v1[j] += __shfl_xor_sync(0xffffffffu, v1[j], o);
            v2[j] += __shfl_xor_sync(0xffffffffu, v2[j], o);
        }
    }
    int wh = h >> 5;
    if ((h & 31) == 0) {
        #pragma unroll
        for (int j = 0; j < 4; j++) { red1[tg][wh][j] = v1[j]; red2[tg][wh][j] = v2[j]; }
    }
    __syncthreads();
    #pragma unroll
    for (int j = 0; j < 4; j++) {
        float sum = red1[tg][0][j] + red1[tg][1][j];
        float sq  = red2[tg][0][j] + red2[tg][1][j];
        float mean = sum * (1.f / 64.f);
        float var  = sq * (1.f / 64.f) - mean * mean;
        float y = (acc[j] - mean) * rsqrtf(var + 1e-5f) * sg[h] + sb[h];
        int node = base + tg * 4 + j;
        g_xc[(size_t)node * MIDc + outOff + h] = fmaxf(y, 0.f);
    }
}

// ================= gather agent rows =================
__global__ void k_gather(const int* __restrict__ loc) {
    int i = blockIdx.x * blockDim.x + threadIdx.x;
    if (i >= Bc * Ac * MIDc) return;
    int r = i / MIDc, k = i - r * MIDc;
    int b = r >> 4;
    int node = b * Nc + loc[r];
    g_ag[i] = g_xc[(size_t)node * MIDc + k];
}

// ========== tensor GEMM via mma.sync bf16 (3-term compensated) ==========
#define SA_H 0
#define SA_L 16896
#define SB_H 33792
#define SB_L 61248
#define TG_SMEM 88704

__device__ __forceinline__ void mma16816(float* c, uint32_t a0, uint32_t a1,
                                         uint32_t a2, uint32_t a3,
                                         uint32_t b0, uint32_t b1) {
    asm volatile(
        "mma.sync.aligned.m16n8k16.row.col.f32.bf16.bf16.f32 "
        "{%0,%1,%2,%3}, {%4,%5,%6,%7}, {%8,%9}, {%0,%1,%2,%3};"
        : "+f"(c[0]), "+f"(c[1]), "+f"(c[2]), "+f"(c[3])
        : "r"(a0), "r"(a1), "r"(a2), "r"(a3), "r"(b0), "r"(b1));
}

__global__ void __launch_bounds__(256, 1) k_tgemm(int mode) {
    const float* A = mode ? g_ag : g_xc;
    float* C       = mode ? g_pre1 : g_np;
    int slice      = mode ? 0 : 1;

    extern __shared__ char smem[];
    uint32_t* sAh = reinterpret_cast<uint32_t*>(smem + SA_H);
    uint32_t* sAl = reinterpret_cast<uint32_t*>(smem + SA_L);
    uint32_t* sBh = reinterpret_cast<uint32_t*>(smem + SB_H);
    uint32_t* sBl = reinterpret_cast<uint32_t*>(smem + SB_L);

    int tid = threadIdx.x;
    int wid = tid >> 5, lane = tid & 31;
    int gid = lane >> 2, tig = lane & 3;
    int bm = blockIdx.x * 128;
    int m0 = wid * 16;
    const uint32_t* Bh = g_Bh + slice * (MIDc * 128);
    const uint32_t* Bl = g_Bl + slice * (MIDc * 128);

    float acc[26][4];
    #pragma unroll
    for (int j = 0; j < 26; j++)
        #pragma unroll
        for (int q = 0; q < 4; q++) acc[j][q] = 0.f;

    for (int c = 0; c < 4; c++) {
        #pragma unroll
        for (int t = 0; t < 16; t++) {
            int i = tid + t * 256;
            int row = i >> 5, w = i & 31;
            int gk = c * 64 + 2 * w;
            float a0 = 0.f, a1 = 0.f;
            if (gk < MIDc) {
                float2 v = *reinterpret_cast<const float2*>(&A[(size_t)(bm + row) * MIDc + gk]);
                a0 = v.x; a1 = v.y;
            }
            __nv_bfloat16 h0 = __float2bfloat16(a0), h1 = __float2bfloat16(a1);
            __nv_bfloat16 l0 = __float2bfloat16(a0 - __bfloat162float(h0));
            __nv_bfloat16 l1 = __float2bfloat16(a1 - __bfloat162float(h1));
            sAh[row * 33 + w] = (uint32_t)__bfloat16_as_ushort(h0) | ((uint32_t)__bfloat16_as_ushort(h1) << 16);
            sAl[row * 33 + w] = (uint32_t)__bfloat16_as_ushort(l0) | ((uint32_t)__bfloat16_as_ushort(l1) << 16);
        }
        #pragma unroll
        for (int t = 0; t < 26; t++) {
            int i = tid + t * 256;
            int n = i >> 5, w = i & 31;
            sBh[n * 33 + w] = Bh[n * 128 + c * 32 + w];
            sBl[n * 33 + w] = Bl[n * 128 + c * 32 + w];
        }
        __syncthreads();

        int nks = (c < 3) ? 4 : 1;
        for (int ks = 0; ks < nks; ks++) {
            int kb = ks * 8;
            int ra = (m0 + gid) * 33 + kb + tig;
            uint32_t ah0 = sAh[ra],       ah1 = sAh[ra + 264];
            uint32_t ah2 = sAh[ra + 4],   ah3 = sAh[ra + 268];
            uint32_t al0 = sAl[ra],       al1 = sAl[ra + 264];
            uint32_t al2 = sAl[ra + 4],   al3 = sAl[ra + 268];
            #pragma unroll
            for (int j = 0; j < 26; j++) {
                int rb = (j * 8 + gid) * 33 + kb + tig;
                uint32_t bh0 = sBh[rb], bh1 = sBh[rb + 4];
                uint32_t bl0 = sBl[rb], bl1 = sBl[rb + 4];
                mma16816(acc[j], ah0, ah1, ah2, ah3, bh0, bh1);
                mma16816(acc[j], al0, al1, al2, al3, bh0, bh1);
                mma16816(acc[j], ah0, ah1, ah2, ah3, bl0, bl1);
            }
        }
        __syncthreads();
    }

    int r0 = bm + m0 + gid, r1 = r0 + 8;
    #pragma unroll
    for (int j = 0; j < 26; j++) {
        int n0 = j * 8 + 2 * tig;
        *reinterpret_cast<float2*>(&C[(size_t)r0 * MIDc + n0]) = make_float2(acc[j][0], acc[j][1]);
        *reinterpret_cast<float2*>(&C[(size_t)r1 * MIDc + n0]) = make_float2(acc[j][2], acc[j][3]);
    }
}

// ================= edge projection =================
__global__ void k_ewp(const float* __restrict__ eW, const float* __restrict__ eb,
                      const float* __restrict__ W1, const float* __restrict__ b1) {
    int m = threadIdx.x;
    if (m >= MIDc) return;
    float s = 0.f, t = 0.f;
    #pragma unroll 8
    for (int h2 = 0; h2 < Hc; h2++) {
        float w = W1[(size_t)(2 * MIDc + h2) * MIDc + m];
        s = fmaf(eW[h2], w, s);
        t = fmaf(eb[h2], w, t);
    }
    g_ewp[m] = s;
    g_cb[m]  = t + b1[m];
}

// ================= dist row/col sums =================
__global__ void __launch_bounds__(512) k_dsums(const int* __restrict__ loc,
                                               const float* __restrict__ dist) {
    int b = blockIdx.x, tid = threadIdx.x;
    __shared__ int sloc[Ac];
    __shared__ float rsd[16];
    if (tid < Ac) sloc[tid] = loc[b * Ac + tid];
    __syncthreads();
    float sd2 = 0.f;
    #pragma unroll
    for (int half = 0; half < 2; half++) {
        int n = tid + half * 512;
        float D = 0.f;
        #pragma unroll
        for (int a = 0; a < Ac; a++) {
            float d = dist[(size_t)sloc[a] * Nc + n];
            D += d;
            sd2 = fmaf(d, d, sd2);
        }
        g_D[b * Nc + n] = D;
    }
    #pragma unroll
    for (int o = 16; o; o >>= 1) sd2 += __shfl_xor_sync(0xffffffffu, sd2, o);
    if ((tid & 31) == 0) rsd[tid >> 5] = sd2;
    __syncthreads();
    if (tid < 16) {
        float v = rsd[tid];
        #pragma unroll
        for (int o = 8; o; o >>= 1) v += __shfl_xor_sync(0x0000ffffu, v, o);
        if (tid == 0) g_sd2p[b] = v;
    }
    int w = tid >> 5, lane = tid & 31;
    if (w < Ac) {
        const float* row = dist + (size_t)sloc[w] * Nc;
        float s = 0.f;
        for (int n = lane; n < Nc; n += 32) s += row[n];
        #pragma unroll
        for (int o = 16; o; o >>= 1) s += __shfl_xor_sync(0xffffffffu, s, o);
        if (lane == 0) g_Da[b * Ac + w] = s;
    }
}

// ================= stats sweep over node_proj =================
__global__ void __launch_bounds__(256) k_stats2() {
    int blk = blockIdx.x;
    int base = blk * 128;
    int tid = threadIdx.x;
    __shared__ float sD[128];
    if (tid < 128) sD[tid] = g_D[base + tid];
    __syncthreads();
    if (tid >= MIDc) return;
    int m = tid;
    float s1 = 0.f, s2 = 0.f, sd = 0.f;
    for (int r = 0; r < 128; r++) {
        float u = g_np[(size_t)(base + r) * MIDc + m];
        s1 += u;
        s2 = fmaf(u, u, s2);
        sd = fmaf(u, sD[r], sd);
    }
    g_p2[(size_t)blk * 3 * MIDc + m]            = s1;
    g_p2[(size_t)blk * 3 * MIDc + MIDc + m]     = s2;
    g_p2[(size_t)blk * 3 * MIDc + 2 * MIDc + m] = sd;
}

// ================= closed-form BN reduce =================
__global__ void __launch_bounds__(256) k_reduce2(const float* __restrict__ bn_g,
                                                 const float* __restrict__ bn_b) {
    int tid = threadIdx.x;
    __shared__ float sDa[Bc * Ac];
    for (int i = tid; i < Bc * Ac; i += 256) sDa[i] = g_Da[i];
    __syncthreads();
    if (tid >= MIDc) return;
    int m = tid;
    float SD = 0.f, SD2 = 0.f;
    for (int i = 0; i < Bc * Ac; i++) SD += sDa[i];
    for (int b = 0; b < Bc; b++) SD2 += g_sd2p[b];
    double c_ = (double)g_cb[m], e = (double)g_ewp[m];
    float S2np = 0.f, SnpD = 0.f, S2v = 0.f, SvDa = 0.f;
    double S1np = 0.0, S1v = 0.0, cross = 0.0;
    for (int b = 0; b < Bc; b++) {
        float s1b = 0.f;
        for (int c = 0; c < 8; c++) {
            int ch = b * 8 + c;
            s1b  += g_p2[(size_t)ch * 3 * MIDc + m];
            S2np += g_p2[(size_t)ch * 3 * MIDc + MIDc + m];
            SnpD += g_p2[(size_t)ch * 3 * MIDc + 2 * MIDc + m];
        }
        float s1vb = 0.f;
        for (int a = 0; a < Ac; a++) {
            float v = g_pre1[(size_t)(b * Ac + a) * MIDc + m];
            s1vb += v;
            S2v  = fmaf(v, v, S2v);
            SvDa = fmaf(v, sDa[b * Ac + a], SvDa);
        }
        S1np += (double)s1b;
        S1v  += (double)s1vb;
        cross += ((double)s1b + (double)Nc * c_) * (double)s1vb;
    }
    double S1u = S1np + (double)NODES * c_;
    double S2u = (double)S2np + 2.0 * c_ * S1np + (double)NODES * c_ * c_;
    double SuD = (double)SnpD + c_ * (double)SD;
    double s1 = (double)Ac * S1u + (double)Nc * S1v + e * (double)SD;
    double s2 = (double)Ac * S2u + (double)Nc * (double)S2v + e * e * (double)SD2
              + 2.0 * cross + 2.0 * e * SuD + 2.0 * e * (double)SvDa;
    double inv = 1.0 / (double)ROWSc;
    double mu = s1 * inv;
    double var = s2 * inv - mu * mu;
    float al = bn_g[m] * (float)rsqrt(var + 1e-5);
    g_alpha[m] = al;
    g_beta[m]  = bn_b[m] - (float)mu * al;
}

// ================= final logits (register-resident P/Q/w2, 1 LDS/elem) ======
__global__ void __launch_bounds__(512) k_final(const int* __restrict__ loc,
                                               const float* __restrict__ dist,
                                               const float* __restrict__ W2,
                                               const float* __restrict__ b2,
                                               const int* __restrict__ mask) {
    int chunk = blockIdx.x;
    int p0 = chunk * 16;
    int b = p0 >> 10;
    int tid = threadIdx.x;
    int a = tid >> 5, lane = tid & 31;
    __shared__ float S[16][224];                 // al * node_proj, zero-padded
    __shared__ float sal[224], sbe[224], scb[224], sewp[224], sw2[224];
    __shared__ float sd[16][Ac];
    __shared__ int sloc[Ac];
    for (int i = tid; i < 224; i += 512) {
        bool v = i < MIDc;
        sal[i] = v ? g_alpha[i] : 0.f;
        sbe[i] = v ? g_beta[i] : 0.f;
        scb[i] = v ? g_cb[i]   : 0.f;
        sewp[i] = v ? g_ewp[i] : 0.f;
        sw2[i] = v ? W2[i]     : 0.f;
    }
    if (tid < Ac) sloc[tid] = loc[b * Ac + tid];
    __syncthreads();
    // S = al * np (padded cols zero)
    for (int i = tid; i < 16 * 224; i += 512) {
        int r = i / 224, c = i - r * 224;
        S[r][c] = (c < MIDc) ? sal[c] * g_np[(size_t)(p0 + r) * MIDc + c] : 0.f;
    }
    for (int i = tid; i < 16 * Ac; i += 512) {
        int r = i >> 4, aa = i & 15;
        int n = (p0 + r) & 1023;
        sd[r][aa] = dist[(size_t)sloc[aa] * Nc + n];
    }
    // per-thread constants: m = q*32 + lane (zero beyond 207 via padded params)
    float P[7], Q[7], Wr[7];
    #pragma unroll
    for (int q = 0; q < 7; q++) {
        int m = q * 32 + lane;
        float al = sal[m];
        float sp = (m < MIDc) ? g_pre1[(size_t)(b * Ac + a) * MIDc + m] : 0.f;
        P[q] = fmaf(al, sp + scb[m], sbe[m]);
        Q[q] = al * sewp[m];
        Wr[q] = sw2[m];
    }
    __syncthreads();
    float bb2 = b2[0];
    for (int ii = 0; ii < 16; ii++) {
        int n = (p0 + ii) & 1023;
        float d = sd[ii][a];
        float part = 0.f;
        #pragma unroll
        for (int q = 0; q < 7; q++) {
            float s = S[ii][q * 32 + lane];
            float arg = fmaf(d, Q[q], s + P[q]);
            part = fmaf(fmaxf(arg, 0.f), Wr[q], part);
        }
        #pragma unroll
        for (int o = 16; o; o >>= 1) part += __shfl_xor_sync(0xffffffffu, part, o);
        if (lane == 0) {
            int ridx = b * (Ac * Nc) + a * Nc + n;
            g_logits[ridx] = (mask[ridx] != 0) ? (part + bb2) : -1e8f;
        }
    }
}

// ================= softmax: partial (max,sumexp) per 2048-slice =============
__global__ void __launch_bounds__(512) k_smax1() {
    int slice = blockIdx.x;          // 0..255
    int b = slice >> 3;
    const float* L = g_logits + (size_t)b * (Ac * Nc) + (slice & 7) * 2048;
    int tid = threadIdx.x;
    float v[4];
    #pragma unroll
    for (int j = 0; j < 4; j++) v[j] = L[tid + j * 512];
    float mx = fmaxf(fmaxf(v[0], v[1]), fmaxf(v[2], v[3]));
    __shared__ float red[16];
    #pragma unroll
    for (int o = 16; o; o >>= 1) mx = fmaxf(mx, __shfl_xor_sync(0xffffffffu, mx, o));
    if ((tid & 31) == 0) red[tid >> 5] = mx;
    __syncthreads();
    if (tid < 16) {
        float t = red[tid];
        #pragma unroll
        for (int o = 8; o; o >>= 1) t = fmaxf(t, __shfl_xor_sync(0x0000ffffu, t, o));
        if (tid == 0) red[0] = t;
    }
    __syncthreads();
    mx = red[0];
    float s = 0.f;
    #pragma unroll
    for (int j = 0; j < 4; j++) s += expf(v[j] - mx);
    __shared__ float red2[16];
    #pragma unroll
    for (int o = 16; o; o >>= 1) s += __shfl_xor_sync(0xffffffffu, s, o);
    if ((tid & 31) == 0) red2[tid >> 5] = s;
    __syncthreads();
    if (tid < 16) {
        float t = red2[tid];
        #pragma unroll
        for (int o = 8; o; o >>= 1) t += __shfl_xor_sync(0x0000ffffu, t, o);
        if (tid == 0) { g_smx[slice * 2] = mx; g_smx[slice * 2 + 1] = t; }
    }
}

// ================= softmax: combine + normalize =============================
__global__ void __launch_bounds__(512) k_smax2(float* __restrict__ out) {
    int slice = blockIdx.x;
    int b = slice >> 3;
    size_t off = (size_t)b * (Ac * Nc) + (slice & 7) * 2048;
    // combine the batch's 8 partials
    float M = -3.4028235e38f;
    #pragma unroll
    for (int j = 0; j < 8; j++) M = fmaxf(M, g_smx[(b * 8 + j) * 2]);
    float Ssum = 0.f;
    #pragma unroll
    for (int j = 0; j < 8; j++)
        Ssum += g_smx[(b * 8 + j) * 2 + 1] * expf(g_smx[(b * 8 + j) * 2] - M);
    float inv = 1.f / Ssum;
    int tid = threadIdx.x;
    const float* L = g_logits + off;
    float* O = out + off;
    #pragma unroll
    for (int j = 0; j < 4; j++) {
        int i = tid + j * 512;
        O[i] = expf(L[i] - M) * inv;
    }
}

// ---------------- launch ----------------
extern "C" void kernel_launch(void* const* d_in, const int* in_sizes, int n_in,
                              void* d_out, int out_size) {
    const float* gnodes = (const float*)d_in[0];
    const int*   links  = (const int*)d_in[1];
    const int*   loc    = (const int*)d_in[2];
    const int*   mask   = (const int*)d_in[3];
    const float* dist   = (const float*)d_in[4];
    const float* cW[3]  = {(const float*)d_in[5],  (const float*)d_in[9],  (const float*)d_in[13]};
    const float* cb_[3] = {(const float*)d_in[6],  (const float*)d_in[10], (const float*)d_in[14]};
    const float* cg[3]  = {(const float*)d_in[7],  (const float*)d_in[11], (const float*)d_in[15]};
    const float* cbe[3] = {(const float*)d_in[8],  (const float*)d_in[12], (const float*)d_in[16]};
    const float* eW  = (const float*)d_in[17];
    const float* eb  = (const float*)d_in[18];
    const float* W1  = (const float*)d_in[19];
    const float* b1  = (const float*)d_in[20];
    const float* bng = (const float*)d_in[21];
    const float* bnb = (const float*)d_in[22];
    const float* W2  = (const float*)d_in[23];
    const float* b2  = (const float*)d_in[24];
    float* out = (float*)d_out;

    cudaFuncSetAttribute(k_tgemm, cudaFuncAttributeMaxDynamicSharedMemorySize, TG_SMEM);

    // CSR build
    k_zero2<<<(NODES + 255) / 256, 256>>>();
    k_count<<<(NEDGE + 255) / 256, 256>>>(links);
    k_scan<<<Bc, 1024>>>();
    k_fill<<<(NEDGE + 255) / 256, 256>>>(links);

    // W hi/lo planes
    k_prepW<<<(2 * MIDc * 128 + 255) / 256, 256>>>(W1);

    // fused conv layers
    k_conv<FINc><<<NODES / 32, 512>>>(gnodes, cW[0], cb_[0], cg[0], cbe[0], 0);
    k_conv<Hc>  <<<NODES / 32, 512>>>(gnodes, cW[1], cb_[1], cg[1], cbe[1], 1);
    k_conv<Hc>  <<<NODES / 32, 512>>>(gnodes, cW[2], cb_[2], cg[2], cbe[2], 2);

    // gather agent rows
    k_gather<<<(Bc * Ac * MIDc + 255) / 256, 256>>>(loc);

    // tensor-core GEMMs
    k_tgemm<<<(Bc * Ac) / 128, 256, TG_SMEM>>>(1);
    k_tgemm<<<NODES / 128, 256, TG_SMEM>>>(0);

    // edge projection + dist sums
    k_ewp<<<1, 256>>>(eW, eb, W1, b1);
    k_dsums<<<Bc, 512>>>(loc, dist);

    // BN stats
    k_stats2<<<NSCHUNK, 256>>>();
    k_reduce2<<<1, 256>>>(bng, bnb);

    // final logits + parallel softmax
    k_final<<<NFCHUNK, 512>>>(loc, dist, W2, b2, mask);
    k_smax1<<<256, 512>>>();
    k_smax2<<<256, 512>>>(out);
}

// round 12
// speedup vs baseline: 3.3432x; 1.1196x over previous
#include <cuda_runtime.h>
#include <cuda_bf16.h>
#include <cstdint>

// ---------------- problem constants ----------------
#define Bc    32
#define Nc    1024
#define Ac    16
#define Ec    4096
#define FINc  16
#define Hc    64
#define MIDc  208          // F_IN + 3*H
#define NODES 32768        // B*N
#define ROWSc 524288       // B*A*N
#define NEDGE 131072       // B*E
#define NFCHUNK 2048       // final chunks (16 nodes each)
#define NSCHUNK 256        // stats chunks (128 nodes each)

// ---------------- scratch (device globals; referenced ONLY from device code) --
__device__ float g_xc[NODES * MIDc];
__device__ float g_np[NODES * MIDc];
__device__ float g_pre1[Bc * Ac * MIDc];
__device__ float g_ewp[MIDc];
__device__ float g_cb[MIDc];
__device__ float g_alpha[MIDc];
__device__ float g_beta[MIDc];
__device__ float g_logits[ROWSc];
// CSR
__device__ int   g_rowptr[NODES + 1];
__device__ int   g_col[NEDGE];
// closed-form BN stats
__device__ float g_D[NODES];
__device__ float g_Da[Bc * Ac];
__device__ float g_sd2p[Bc];
__device__ float g_p2[NSCHUNK * 3 * MIDc];
// per-chunk softmax partials (max, sumexp)
__device__ float g_smx[NFCHUNK * 2];
// W bf16 hi/lo planes, [slice][n][kpair]; K padded 208->256
__device__ unsigned int g_Bh[2 * MIDc * 128];
__device__ unsigned int g_Bl[2 * MIDc * 128];

// ================= CSR + dist sums (one kernel, block = batch) =============
__global__ void __launch_bounds__(1024) k_csrd(const int* __restrict__ links,
                                               const int* __restrict__ loc,
                                               const float* __restrict__ dist) {
    int b = blockIdx.x, t = threadIdx.x;
    __shared__ int cnt[1024];
    __shared__ int sc[1024];
    __shared__ int fil[1024];
    __shared__ int sloc[Ac];
    __shared__ float rsd[32];
    cnt[t] = 0; fil[t] = 0;
    if (t < Ac) sloc[t] = loc[b * Ac + t];
    __syncthreads();
    const int* lb = links + b * 2 * Ec;
    #pragma unroll
    for (int e = t; e < Ec; e += 1024) atomicAdd(&cnt[lb[Ec + e]], 1);
    // ---- dist sums (independent of cnt) ----
    float D = 0.f, sd2 = 0.f;
    #pragma unroll
    for (int a = 0; a < Ac; a++) {
        float d = dist[(size_t)sloc[a] * Nc + t];
        D += d;
        sd2 = fmaf(d, d, sd2);
    }
    g_D[b * Nc + t] = D;
    __syncthreads();
    // ---- inclusive scan of cnt ----
    sc[t] = cnt[t];
    __syncthreads();
    for (int off = 1; off < 1024; off <<= 1) {
        int x = (t >= off) ? sc[t - off] : 0;
        __syncthreads();
        sc[t] += x;
        __syncthreads();
    }
    int base = sc[t] - cnt[t];
    g_rowptr[b * Nc + t] = b * Ec + base;
    if (b == Bc - 1 && t == 1023) g_rowptr[NODES] = NEDGE;
    __syncthreads();
    cnt[t] = base;            // reuse cnt[] as base
    __syncthreads();
    #pragma unroll
    for (int e = t; e < Ec; e += 1024) {
        int src = lb[e], dst = lb[Ec + e];
        int pos = b * Ec + cnt[dst] + atomicAdd(&fil[dst], 1);
        g_col[pos] = b * Nc + src;
    }
    // ---- sd2 block reduce ----
    #pragma unroll
    for (int o = 16; o; o >>= 1) sd2 += __shfl_xor_sync(0xffffffffu, sd2, o);
    if ((t & 31) == 0) rsd[t >> 5] = sd2;
    __syncthreads();
    if (t < 32) {
        float v = rsd[t];
        #pragma unroll
        for (int o = 16; o; o >>= 1) v += __shfl_xor_sync(0xffffffffu, v, o);
        if (t == 0) g_sd2p[b] = v;
    }
    // ---- Da: warps 0..15 ----
    int w = t >> 5, lane = t & 31;
    if (w < Ac) {
        const float* row = dist + (size_t)sloc[w] * Nc;
        float s = 0.f;
        for (int n = lane; n < Nc; n += 32) s += row[n];
        #pragma unroll
        for (int o = 16; o; o >>= 1) s += __shfl_xor_sync(0xffffffffu, s, o);
        if (lane == 0) g_Da[b * Ac + w] = s;
    }
}

// ================= W -> bf16 hi/lo planes, B^T layout [n][kpair] =========
__global__ void k_prepW(const float* __restrict__ W1) {
    int i = blockIdx.x * blockDim.x + threadIdx.x;
    if (i >= 2 * MIDc * 128) return;
    int s = i / (MIDc * 128);
    int rem = i - s * (MIDc * 128);
    int n  = rem >> 7;
    int kp = rem & 127;
    int k0 = 2 * kp;
    float w0 = (k0     < MIDc) ? W1[(size_t)(s * MIDc + k0)     * MIDc + n] : 0.f;
    float w1 = (k0 + 1 < MIDc) ? W1[(size_t)(s * MIDc + k0 + 1) * MIDc + n] : 0.f;
    __nv_bfloat16 h0 = __float2bfloat16(w0), h1 = __float2bfloat16(w1);
    __nv_bfloat16 l0 = __float2bfloat16(w0 - __bfloat162float(h0));
    __nv_bfloat16 l1 = __float2bfloat16(w1 - __bfloat162float(h1));
    g_Bh[i] = (uint32_t)__bfloat16_as_ushort(h0) | ((uint32_t)__bfloat16_as_ushort(h1) << 16);
    g_Bl[i] = (uint32_t)__bfloat16_as_ushort(l0) | ((uint32_t)__bfloat16_as_ushort(l1) << 16);
}

// ================= fused conv (gather-agg + MLP + LN + ReLU) =================
template <int F>
__global__ void __launch_bounds__(512) k_conv(const float* __restrict__ gnodes,
                                              const float* __restrict__ W,
                                              const float* __restrict__ bias,
                                              const float* __restrict__ gg,
                                              const float* __restrict__ beta,
                                              int layer) {
    const float* X;
    int xs, outOff;
    if (layer == 0)      { X = gnodes;    xs = FINc; outOff = 16; }
    else if (layer == 1) { X = g_xc + 16; xs = MIDc; outOff = 80; }
    else                 { X = g_xc + 80; xs = MIDc; outOff = 144; }

    int tid = threadIdx.x;
    int h = tid & 63, tg = tid >> 6;
    int base = blockIdx.x * 32;
    __shared__ float sW[F * 64];
    __shared__ float sagg[32][64];
    __shared__ float sbias[64], sg[64], sb[64];
    __shared__ float red1[8][2][4], red2[8][2][4];
    if (layer == 0) {
        int node = base + (tid >> 4);
        g_xc[(size_t)node * MIDc + (tid & 15)] = gnodes[(size_t)node * FINc + (tid & 15)];
    }
    for (int i = tid; i < F * 64; i += 512) sW[i] = W[i];
    if (tid < 64) { sbias[tid] = bias[tid]; sg[tid] = gg[tid]; sb[tid] = beta[tid]; }
    if (h < F) {
        #pragma unroll
        for (int j = 0; j < 4; j++) {
            int node = base + tg * 4 + j;
            int p0 = g_rowptr[node], p1 = g_rowptr[node + 1];
            float s = 0.f;
            for (int p = p0; p < p1; p++) s += X[(size_t)g_col[p] * xs + h];
            sagg[tg * 4 + j][h] = s;
        }
    }
    __syncthreads();
    float acc[4];
    #pragma unroll
    for (int j = 0; j < 4; j++) acc[j] = sbias[h];
    #pragma unroll
    for (int f = 0; f < F; f += 4) {
        float w0 = sW[(f + 0) * 64 + h];
        float w1 = sW[(f + 1) * 64 + h];
        float w2 = sW[(f + 2) * 64 + h];
        float w3 = sW[(f + 3) * 64 + h];
        #pragma unroll
        for (int j = 0; j < 4; j++) {
            float4 a = *reinterpret_cast<const float4*>(&sagg[tg * 4 + j][f]);
            acc[j] = fmaf(a.x, w0, acc[j]);
            acc[j] = fmaf(a.y, w1, acc[j]);
            acc[j] = fmaf(a.z, w2, acc[j]);
            acc[j] = fmaf(a.w, w3, acc[j]);
        }
    }
    float v1[4], v2[4];
    #pragma unroll
    for (int j = 0; j < 4; j++) { v1[j] = acc[j]; v2[j] = acc[j] * acc[j]; }
    #pragma unroll
    for (int o = 16; o; o >>= 1) {
        #pragma unroll
        for (int j = 0; j < 4; j++) {
            v1[j] += __shfl_xor_sync(0xffffffffu, v1[j], o);
            v2[j] += __shfl_xor_sync(0xffffffffu, v2[j], o);
        }
    }
    int wh = h >> 5;
    if ((h & 31) == 0) {
        #pragma unroll
        for (int j = 0; j < 4; j++) { red1[tg][wh][j] = v1[j]; red2[tg][wh][j] = v2[j]; }
    }
    __syncthreads();
    #pragma unroll
    for (int j = 0; j < 4; j++) {
        float sum = red1[tg][0][j] + red1[tg][1][j];
        float sq  = red2[tg][0][j] + red2[tg][1][j];
        float mean = sum * (1.f / 64.f);
        float var  = sq * (1.f / 64.f) - mean * mean;
        float y = (acc[j] - mean) * rsqrtf(var + 1e-5f) * sg[h] + sb[h];
        int node = base + tg * 4 + j;
        g_xc[(size_t)node * MIDc + outOff + h] = fmaxf(y, 0.f);
    }
}

// ========== tensor GEMM via mma.sync bf16 (3-term compensated) ==========
// One launch, 260 CTAs. Blocks 0..3: pre1 (A rows via loc gather, slice 0).
// Blocks 4..259: np (A = g_xc, slice 1).
#define SA_H 0
#define SA_L 16896
#define SB_H 33792
#define SB_L 61248
#define TG_SMEM 88704

__device__ __forceinline__ void mma16816(float* c, uint32_t a0, uint32_t a1,
                                         uint32_t a2, uint32_t a3,
                                         uint32_t b0, uint32_t b1) {
    asm volatile(
        "mma.sync.aligned.m16n8k16.row.col.f32.bf16.bf16.f32 "
        "{%0,%1,%2,%3}, {%4,%5,%6,%7}, {%8,%9}, {%0,%1,%2,%3};"
        : "+f"(c[0]), "+f"(c[1]), "+f"(c[2]), "+f"(c[3])
        : "r"(a0), "r"(a1), "r"(a2), "r"(a3), "r"(b0), "r"(b1));
}

__global__ void __launch_bounds__(256, 1) k_tgemm(const int* __restrict__ loc) {
    bool small = blockIdx.x < 4;
    int slice  = small ? 0 : 1;
    float* C   = small ? g_pre1 : g_np;
    int bm     = (small ? blockIdx.x : (blockIdx.x - 4)) * 128;

    extern __shared__ char smem[];
    uint32_t* sAh = reinterpret_cast<uint32_t*>(smem + SA_H);
    uint32_t* sAl = reinterpret_cast<uint32_t*>(smem + SA_L);
    uint32_t* sBh = reinterpret_cast<uint32_t*>(smem + SB_H);
    uint32_t* sBl = reinterpret_cast<uint32_t*>(smem + SB_L);

    int tid = threadIdx.x;
    int wid = tid >> 5, lane = tid & 31;
    int gid = lane >> 2, tig = lane & 3;
    int m0 = wid * 16;
    const uint32_t* Bh = g_Bh + slice * (MIDc * 128);
    const uint32_t* Bl = g_Bl + slice * (MIDc * 128);

    float acc[26][4];
    #pragma unroll
    for (int j = 0; j < 26; j++)
        #pragma unroll
        for (int q = 0; q < 4; q++) acc[j][q] = 0.f;

    for (int c = 0; c < 4; c++) {
        #pragma unroll
        for (int t = 0; t < 16; t++) {
            int i = tid + t * 256;
            int row = i >> 5, w = i & 31;
            int gk = c * 64 + 2 * w;
            // resolve A row (gather for the agent GEMM)
            int ar = bm + row;
            size_t abase;
            if (small) {
                int node = (ar >> 4) * Nc + loc[ar];
                abase = (size_t)node * MIDc;
            } else {
                abase = (size_t)ar * MIDc;
            }
            float a0 = 0.f, a1 = 0.f;
            if (gk < MIDc) {
                float2 v = *reinterpret_cast<const float2*>(&g_xc[abase + gk]);
                a0 = v.x; a1 = v.y;
            }
            __nv_bfloat16 h0 = __float2bfloat16(a0), h1 = __float2bfloat16(a1);
            __nv_bfloat16 l0 = __float2bfloat16(a0 - __bfloat162float(h0));
            __nv_bfloat16 l1 = __float2bfloat16(a1 - __bfloat162float(h1));
            sAh[row * 33 + w] = (uint32_t)__bfloat16_as_ushort(h0) | ((uint32_t)__bfloat16_as_ushort(h1) << 16);
            sAl[row * 33 + w] = (uint32_t)__bfloat16_as_ushort(l0) | ((uint32_t)__bfloat16_as_ushort(l1) << 16);
        }
        #pragma unroll
        for (int t = 0; t < 26; t++) {
            int i = tid + t * 256;
            int n = i >> 5, w = i & 31;
            sBh[n * 33 + w] = Bh[n * 128 + c * 32 + w];
            sBl[n * 33 + w] = Bl[n * 128 + c * 32 + w];
        }
        __syncthreads();

        int nks = (c < 3) ? 4 : 1;
        for (int ks = 0; ks < nks; ks++) {
            int kb = ks * 8;
            int ra = (m0 + gid) * 33 + kb + tig;
            uint32_t ah0 = sAh[ra],       ah1 = sAh[ra + 264];
            uint32_t ah2 = sAh[ra + 4],   ah3 = sAh[ra + 268];
            uint32_t al0 = sAl[ra],       al1 = sAl[ra + 264];
            uint32_t al2 = sAl[ra + 4],   al3 = sAl[ra + 268];
            #pragma unroll
            for (int j = 0; j < 26; j++) {
                int rb = (j * 8 + gid) * 33 + kb + tig;
                uint32_t bh0 = sBh[rb], bh1 = sBh[rb + 4];
                uint32_t bl0 = sBl[rb], bl1 = sBl[rb + 4];
                mma16816(acc[j], ah0, ah1, ah2, ah3, bh0, bh1);
                mma16816(acc[j], al0, al1, al2, al3, bh0, bh1);
                mma16816(acc[j], ah0, ah1, ah2, ah3, bl0, bl1);
            }
        }
        __syncthreads();
    }

    int r0 = bm + m0 + gid, r1 = r0 + 8;
    #pragma unroll
    for (int j = 0; j < 26; j++) {
        int n0 = j * 8 + 2 * tig;
        *reinterpret_cast<float2*>(&C[(size_t)r0 * MIDc + n0]) = make_float2(acc[j][0], acc[j][1]);
        *reinterpret_cast<float2*>(&C[(size_t)r1 * MIDc + n0]) = make_float2(acc[j][2], acc[j][3]);
    }
}

// ================= stats sweep over node_proj =================
__global__ void __launch_bounds__(256) k_stats2() {
    int blk = blockIdx.x;
    int base = blk * 128;
    int tid = threadIdx.x;
    __shared__ float sD[128];
    if (tid < 128) sD[tid] = g_D[base + tid];
    __syncthreads();
    if (tid >= MIDc) return;
    int m = tid;
    float s1 = 0.f, s2 = 0.f, sd = 0.f;
    for (int r = 0; r < 128; r++) {
        float u = g_np[(size_t)(base + r) * MIDc + m];
        s1 += u;
        s2 = fmaf(u, u, s2);
        sd = fmaf(u, sD[r], sd);
    }
    g_p2[(size_t)blk * 3 * MIDc + m]            = s1;
    g_p2[(size_t)blk * 3 * MIDc + MIDc + m]     = s2;
    g_p2[(size_t)blk * 3 * MIDc + 2 * MIDc + m] = sd;
}

// ================= closed-form BN reduce (ewp inlined) ======================
__global__ void __launch_bounds__(256) k_reduce2(const float* __restrict__ bn_g,
                                                 const float* __restrict__ bn_b,
                                                 const float* __restrict__ eW,
                                                 const float* __restrict__ eb,
                                                 const float* __restrict__ W1,
                                                 const float* __restrict__ b1) {
    int tid = threadIdx.x;
    __shared__ float sDa[Bc * Ac];
    for (int i = tid; i < Bc * Ac; i += 256) sDa[i] = g_Da[i];
    __syncthreads();
    if (tid >= MIDc) return;
    int m = tid;
    // inline edge projection
    float ef = 0.f, cf = 0.f;
    #pragma unroll 8
    for (int h2 = 0; h2 < Hc; h2++) {
        float w = W1[(size_t)(2 * MIDc + h2) * MIDc + m];
        ef = fmaf(eW[h2], w, ef);
        cf = fmaf(eb[h2], w, cf);
    }
    cf += b1[m];
    g_ewp[m] = ef;
    g_cb[m]  = cf;
    float SD = 0.f, SD2 = 0.f;
    for (int i = 0; i < Bc * Ac; i++) SD += sDa[i];
    for (int b = 0; b < Bc; b++) SD2 += g_sd2p[b];
    double c_ = (double)cf, e = (double)ef;
    float S2np = 0.f, SnpD = 0.f, S2v = 0.f, SvDa = 0.f;
    double S1np = 0.0, S1v = 0.0, cross = 0.0;
    for (int b = 0; b < Bc; b++) {
        float s1b = 0.f;
        for (int c = 0; c < 8; c++) {
            int ch = b * 8 + c;
            s1b  += g_p2[(size_t)ch * 3 * MIDc + m];
            S2np += g_p2[(size_t)ch * 3 * MIDc + MIDc + m];
            SnpD += g_p2[(size_t)ch * 3 * MIDc + 2 * MIDc + m];
        }
        float s1vb = 0.f;
        for (int a = 0; a < Ac; a++) {
            float v = g_pre1[(size_t)(b * Ac + a) * MIDc + m];
            s1vb += v;
            S2v  = fmaf(v, v, S2v);
            SvDa = fmaf(v, sDa[b * Ac + a], SvDa);
        }
        S1np += (double)s1b;
        S1v  += (double)s1vb;
        cross += ((double)s1b + (double)Nc * c_) * (double)s1vb;
    }
    double S1u = S1np + (double)NODES * c_;
    double S2u = (double)S2np + 2.0 * c_ * S1np + (double)NODES * c_ * c_;
    double SuD = (double)SnpD + c_ * (double)SD;
    double s1 = (double)Ac * S1u + (double)Nc * S1v + e * (double)SD;
    double s2 = (double)Ac * S2u + (double)Nc * (double)S2v + e * e * (double)SD2
              + 2.0 * cross + 2.0 * e * SuD + 2.0 * e * (double)SvDa;
    double inv = 1.0 / (double)ROWSc;
    double mu = s1 * inv;
    double var = s2 * inv - mu * mu;
    float al = bn_g[m] * (float)rsqrt(var + 1e-5);
    g_alpha[m] = al;
    g_beta[m]  = bn_b[m] - (float)mu * al;
}

// ====== final logits + per-chunk softmax partials (max, sumexp) =============
__global__ void __launch_bounds__(512) k_final(const int* __restrict__ loc,
                                               const float* __restrict__ dist,
                                               const float* __restrict__ W2,
                                               const float* __restrict__ b2,
                                               const int* __restrict__ mask) {
    int chunk = blockIdx.x;
    int p0 = chunk * 16;
    int b = p0 >> 10;
    int tid = threadIdx.x;
    int a = tid >> 5, lane = tid & 31;
    __shared__ float S[16][224];
    __shared__ float sal[224], sbe[224], scb[224], sewp[224], sw2[224];
    __shared__ float sd[16][Ac];
    __shared__ float slg[256];
    __shared__ float red[16];
    __shared__ int sloc[Ac];
    for (int i = tid; i < 224; i += 512) {
        bool v = i < MIDc;
        sal[i] = v ? g_alpha[i] : 0.f;
        sbe[i] = v ? g_beta[i] : 0.f;
        scb[i] = v ? g_cb[i]   : 0.f;
        sewp[i] = v ? g_ewp[i] : 0.f;
        sw2[i] = v ? W2[i]     : 0.f;
    }
    if (tid < Ac) sloc[tid] = loc[b * Ac + tid];
    __syncthreads();
    for (int i = tid; i < 16 * 224; i += 512) {
        int r = i / 224, c = i - r * 224;
        S[r][c] = (c < MIDc) ? sal[c] * g_np[(size_t)(p0 + r) * MIDc + c] : 0.f;
    }
    for (int i = tid; i < 16 * Ac; i += 512) {
        int r = i >> 4, aa = i & 15;
        int n = (p0 + r) & 1023;
        sd[r][aa] = dist[(size_t)sloc[aa] * Nc + n];
    }
    float P[7], Q[7], Wr[7];
    #pragma unroll
    for (int q = 0; q < 7; q++) {
        int m = q * 32 + lane;
        float al = sal[m];
        float sp = (m < MIDc) ? g_pre1[(size_t)(b * Ac + a) * MIDc + m] : 0.f;
        P[q] = fmaf(al, sp + scb[m], sbe[m]);
        Q[q] = al * sewp[m];
        Wr[q] = sw2[m];
    }
    __syncthreads();
    float bb2 = b2[0];
    for (int ii = 0; ii < 16; ii++) {
        int n = (p0 + ii) & 1023;
        float d = sd[ii][a];
        float part = 0.f;
        #pragma unroll
        for (int q = 0; q < 7; q++) {
            float s = S[ii][q * 32 + lane];
            float arg = fmaf(d, Q[q], s + P[q]);
            part = fmaf(fmaxf(arg, 0.f), Wr[q], part);
        }
        #pragma unroll
        for (int o = 16; o; o >>= 1) part += __shfl_xor_sync(0xffffffffu, part, o);
        if (lane == 0) {
            int ridx = b * (Ac * Nc) + a * Nc + n;
            float lg = (mask[ridx] != 0) ? (part + bb2) : -1e8f;
            g_logits[ridx] = lg;
            slg[a * 16 + ii] = lg;
        }
    }
    __syncthreads();
    // block softmax partial over the 256 chunk logits (threads 0..255)
    if (tid < 256) {
        float v = slg[tid];
        float mx = v;
        #pragma unroll
        for (int o = 16; o; o >>= 1) mx = fmaxf(mx, __shfl_xor_sync(0xffffffffu, mx, o));
        if ((tid & 31) == 0) red[tid >> 5] = mx;
        __syncwarp();
    }
    __syncthreads();
    if (tid < 8) {
        float t = red[tid];
        #pragma unroll
        for (int o = 4; o; o >>= 1) t = fmaxf(t, __shfl_xor_sync(0x000000ffu, t, o));
        if (tid == 0) red[8] = t;
    }
    __syncthreads();
    float bmax = red[8];
    if (tid < 256) {
        float s = expf(slg[tid] - bmax);
        #pragma unroll
        for (int o = 16; o; o >>= 1) s += __shfl_xor_sync(0xffffffffu, s, o);
        if ((tid & 31) == 0) red[tid >> 5] = s;
        __syncwarp();
    }
    __syncthreads();
    if (tid < 8) {
        float t = red[tid];
        #pragma unroll
        for (int o = 4; o; o >>= 1) t += __shfl_xor_sync(0x000000ffu, t, o);
        if (tid == 0) {
            g_smx[chunk * 2]     = bmax;
            g_smx[chunk * 2 + 1] = t;
        }
    }
}

// ============ softmax: combine per-batch chunk partials + normalize =========
__global__ void __launch_bounds__(512) k_smax2(float* __restrict__ out) {
    int slice = blockIdx.x;          // 0..255, 8 per batch
    int b = slice >> 3;
    size_t off = (size_t)b * (Ac * Nc) + (slice & 7) * 2048;
    int tid = threadIdx.x;
    __shared__ float sM, sInv;
    __shared__ float red[4];
    // combine 64 chunk partials of this batch (2 warps)
    if (tid < 64) {
        float m = g_smx[(b * 64 + tid) * 2];
        float mx = m;
        #pragma unroll
        for (int o = 16; o; o >>= 1) mx = fmaxf(mx, __shfl_xor_sync(0xffffffffu, mx, o));
        if ((tid & 31) == 0) red[tid >> 5] = mx;
    }
    __syncthreads();
    float M = fmaxf(red[0], red[1]);
    if (tid < 64) {
        float m = g_smx[(b * 64 + tid) * 2];
        float s = g_smx[(b * 64 + tid) * 2 + 1] * expf(m - M);
        #pragma unroll
        for (int o = 16; o; o >>= 1) s += __shfl_xor_sync(0xffffffffu, s, o);
        if ((tid & 31) == 0) red[2 + (tid >> 5)] = s;
    }
    __syncthreads();
    if (tid == 0) { sM = M; sInv = 1.f / (red[2] + red[3]); }
    __syncthreads();
    float Mv = sM, inv = sInv;
    const float* L = g_logits + off;
    float* O = out + off;
    #pragma unroll
    for (int j = 0; j < 4; j++) {
        int i = tid + j * 512;
        O[i] = expf(L[i] - Mv) * inv;
    }
}

// ---------------- launch ----------------
extern "C" void kernel_launch(void* const* d_in, const int* in_sizes, int n_in,
                              void* d_out, int out_size) {
    const float* gnodes = (const float*)d_in[0];
    const int*   links  = (const int*)d_in[1];
    const int*   loc    = (const int*)d_in[2];
    const int*   mask   = (const int*)d_in[3];
    const float* dist   = (const float*)d_in[4];
    const float* cW[3]  = {(const float*)d_in[5],  (const float*)d_in[9],  (const float*)d_in[13]};
    const float* cb_[3] = {(const float*)d_in[6],  (const float*)d_in[10], (const float*)d_in[14]};
    const float* cg[3]  = {(const float*)d_in[7],  (const float*)d_in[11], (const float*)d_in[15]};
    const float* cbe[3] = {(const float*)d_in[8],  (const float*)d_in[12], (const float*)d_in[16]};
    const float* eW  = (const float*)d_in[17];
    const float* eb  = (const float*)d_in[18];
    const float* W1  = (const float*)d_in[19];
    const float* b1  = (const float*)d_in[20];
    const float* bng = (const float*)d_in[21];
    const float* bnb = (const float*)d_in[22];
    const float* W2  = (const float*)d_in[23];
    const float* b2  = (const float*)d_in[24];
    float* out = (float*)d_out;

    cudaFuncSetAttribute(k_tgemm, cudaFuncAttributeMaxDynamicSharedMemorySize, TG_SMEM);

    // W hi/lo planes (independent; first)
    k_prepW<<<(2 * MIDc * 128 + 255) / 256, 256>>>(W1);

    // CSR + dist sums in one kernel
    k_csrd<<<Bc, 1024>>>(links, loc, dist);

    // fused conv layers (layer 0 also copies x0 into xc)
    k_conv<FINc><<<NODES / 32, 512>>>(gnodes, cW[0], cb_[0], cg[0], cbe[0], 0);
    k_conv<Hc>  <<<NODES / 32, 512>>>(gnodes, cW[1], cb_[1], cg[1], cbe[1], 1);
    k_conv<Hc>  <<<NODES / 32, 512>>>(gnodes, cW[2], cb_[2], cg[2], cbe[2], 2);

    // both GEMMs in one launch (gather fused into agent GEMM)
    k_tgemm<<<4 + NODES / 128, 256, TG_SMEM>>>(loc);

    // BN stats
    k_stats2<<<NSCHUNK, 256>>>();
    k_reduce2<<<1, 256>>>(bng, bnb, eW, eb, W1, b1);

    // final logits (+chunk softmax partials) + combine/normalize
    k_final<<<NFCHUNK, 512>>>(loc, dist, W2, b2, mask);
    k_smax2<<<256, 512>>>(out);
}